// round 13
// baseline (speedup 1.0000x reference)
#include <cuda_runtime.h>
#include <cuda_bf16.h>
#include <math.h>
#include <stdint.h>

#define TB 16
#define TS 512
#define TE 1024
#define TH 16
#define TD 64
#define KSPLIT 3072          // 3 * TE (bf16 hi|mid|lo splits along K)

// Scratch (device globals: allocation-free rule)
static __device__ float  g_Q[(size_t)TB * TS * TE];
static __device__ float  g_K[(size_t)TB * TS * TE];
static __device__ double g_colpart[TB * TH * TS];
static __device__ double g_logits[TB * TS];
static __device__ __align__(128) __nv_bfloat16 g_As[(size_t)TB * TS * KSPLIT]; // tokens split
static __device__ __align__(128) __nv_bfloat16 g_Ws[(size_t)2 * TE * KSPLIT];  // Wq/Wk split
// per-head bf16 splits of Q/K: [bh][512 rows][3 segs x 64] (row = 192 bf16)
static __device__ __align__(128) __nv_bfloat16 g_Qs2[(size_t)TB * TH * TS * 192];
static __device__ __align__(128) __nv_bfloat16 g_Ks2[(size_t)TB * TH * TS * 192];

// ---------------------------------------------------------------------------
// PTX helpers (sm_80-class only: mma.sync / ldmatrix / cp.async — NO tcgen05)
// ---------------------------------------------------------------------------
__device__ __forceinline__ uint32_t smem_u32(const void* p) {
    uint32_t a;
    asm("{ .reg .u64 t; cvta.to.shared.u64 t, %1; cvt.u32.u64 %0, t; }" : "=r"(a) : "l"(p));
    return a;
}
#define SW128(o) ((o) ^ ((((uint32_t)(o)) >> 3) & 0x70u))

#define CP_ASYNC16(dst, src) \
    asm volatile("cp.async.cg.shared.global [%0], [%1], 16;" :: "r"(dst), "l"(src))
#define CP_COMMIT()  asm volatile("cp.async.commit_group;" ::: "memory")
#define CP_WAIT1()   asm volatile("cp.async.wait_group 1;" ::: "memory")
#define CP_WAIT0()   asm volatile("cp.async.wait_group 0;" ::: "memory")

#define LDSM_X4(r0, r1, r2, r3, a) \
    asm volatile("ldmatrix.sync.aligned.m8n8.x4.shared.b16 {%0,%1,%2,%3}, [%4];" \
                 : "=r"(r0), "=r"(r1), "=r"(r2), "=r"(r3) : "r"(a))

#define MMA_16816(D, A, B0, B1) \
    asm volatile("mma.sync.aligned.m16n8k16.row.col.f32.bf16.bf16.f32 " \
                 "{%0,%1,%2,%3}, {%4,%5,%6,%7}, {%8,%9}, {%0,%1,%2,%3};" \
                 : "+f"((D)[0]), "+f"((D)[1]), "+f"((D)[2]), "+f"((D)[3]) \
                 : "r"((A)[0]), "r"((A)[1]), "r"((A)[2]), "r"((A)[3]), \
                   "r"(B0), "r"(B1))

// ---------------------------------------------------------------------------
// Deterministic FMA-pipe exp (kept from R12 — neutral but harmless)
// ---------------------------------------------------------------------------
__device__ __forceinline__ float fast_expf(float x) {
    const float LOG2E   = 1.4426950408889634f;
    const float LN2_HI  = 0.693145751953125f;
    const float LN2_LO  = 1.428606765330187e-06f;
    float y  = x * LOG2E;
    float r  = rintf(y);
    int   ri = (int)r;
    float t  = fmaf(-r, LN2_HI, x);
    t = fmaf(-r, LN2_LO, t);
    float p = 1.9841269841e-4f;
    p = fmaf(p, t, 1.3888888889e-3f);
    p = fmaf(p, t, 8.3333333333e-3f);
    p = fmaf(p, t, 4.1666666667e-2f);
    p = fmaf(p, t, 1.6666666667e-1f);
    p = fmaf(p, t, 0.5f);
    p = fmaf(p, t, 1.0f);
    p = fmaf(p, t, 1.0f);
    return p * __int_as_float((ri + 127) << 23);
}

// ---------------------------------------------------------------------------
// Exact 3-way bf16 split
// ---------------------------------------------------------------------------
__device__ __forceinline__ void split3(float x, unsigned short& h, unsigned short& m,
                                       unsigned short& l) {
    __nv_bfloat16 bh = __float2bfloat16_rn(x);
    float r  = x - __bfloat162float(bh);
    __nv_bfloat16 bm = __float2bfloat16_rn(r);
    float r2 = r - __bfloat162float(bm);
    __nv_bfloat16 bl = __float2bfloat16_rn(r2);
    h = __bfloat16_as_ushort(bh);
    m = __bfloat16_as_ushort(bm);
    l = __bfloat16_as_ushort(bl);
}

__device__ __forceinline__ void split_store4s(const float4 v, __nv_bfloat16* dst, int stride) {
    unsigned short h[4], m[4], l[4];
    split3(v.x, h[0], m[0], l[0]);
    split3(v.y, h[1], m[1], l[1]);
    split3(v.z, h[2], m[2], l[2]);
    split3(v.w, h[3], m[3], l[3]);
    uint2 uh = make_uint2((uint32_t)h[0] | ((uint32_t)h[1] << 16),
                          (uint32_t)h[2] | ((uint32_t)h[3] << 16));
    uint2 um = make_uint2((uint32_t)m[0] | ((uint32_t)m[1] << 16),
                          (uint32_t)m[2] | ((uint32_t)m[3] << 16));
    uint2 ul = make_uint2((uint32_t)l[0] | ((uint32_t)l[1] << 16),
                          (uint32_t)l[2] | ((uint32_t)l[3] << 16));
    *(uint2*)(dst)              = uh;
    *(uint2*)(dst + stride)     = um;
    *(uint2*)(dst + 2 * stride) = ul;
}

// fused input split: blocks [0,8192) tokens -> g_As; [8192,9216) Wq; [9216,10240) Wk
__global__ __launch_bounds__(256) void split_inputs_kernel(
    const float* __restrict__ tokens,
    const float* __restrict__ Wq, const float* __restrict__ Wk)
{
    int blk = blockIdx.x;
    if (blk < 8192) {
        size_t i = (size_t)blk * 256 + threadIdx.x;
        float4 v = ((const float4*)tokens)[i];
        size_t row = i >> 8;
        int    c4  = (int)(i & 255) * 4;
        split_store4s(v, g_As + row * KSPLIT + c4, TE);
    } else {
        int sel = (blk >= 9216) ? 1 : 0;
        size_t i = (size_t)(blk - 8192 - sel * 1024) * 256 + threadIdx.x;
        const float* W = sel ? Wk : Wq;
        float4 v = ((const float4*)W)[i];
        size_t row = i >> 8;
        int    c4  = (int)(i & 255) * 4;
        split_store4s(v, g_Ws + (size_t)sel * TE * KSPLIT + row * KSPLIT + c4, TE);
    }
}

// g_Q/g_K fp32 [8192,1024] -> per-head split [bh][512][3*64] bf16
__global__ __launch_bounds__(256) void split_qk_kernel()
{
    const float*    src = blockIdx.z ? g_K : g_Q;
    __nv_bfloat16*  dst = blockIdx.z ? g_Ks2 : g_Qs2;
    size_t i = (size_t)blockIdx.x * 256 + threadIdx.x;
    float4 v = ((const float4*)src)[i];
    size_t r = i >> 8;
    int    c4 = (int)(i & 255) * 4;
    int h = c4 >> 6, d = c4 & 63;
    int b = (int)(r >> 9), s = (int)(r & 511);
    __nv_bfloat16* o = dst + (((size_t)(b * TH + h) * TS + s) * 192 + d);
    split_store4s(v, o, 64);
}

// ---------------------------------------------------------------------------
// HMMA GEMM (unchanged, validated): 6-term bf16-split product
// ---------------------------------------------------------------------------
#define GEMM_STAGES 3
#define GEMM_STAGE_BYTES 32768
#define GEMM_SMEM (GEMM_STAGES * GEMM_STAGE_BYTES)
#define NCHUNK 96

__global__ __launch_bounds__(256) void gemm_hmma_kernel(const float* __restrict__ bq,
                                                        const float* __restrict__ bk)
{
    extern __shared__ char dsm[];
    const uint32_t smem_base = smem_u32(dsm);

    const int t    = threadIdx.x;
    const int lane = t & 31, wid = t >> 5;
    const int warp_m = wid & 3;
    const int warp_n = wid >> 2;
    const int sel = blockIdx.z;
    const int m0  = blockIdx.y * 128;
    const int n0  = blockIdx.x * 128;

    float*       C    = sel ? g_K : g_Q;
    const float* bias = sel ? bk : bq;

    const int row  = t >> 1;
    const int half = t & 1;
    const char* aG = (const char*)(g_As + (size_t)(m0 + row) * KSPLIT + half * 32);
    const char* bG = (const char*)(g_Ws + (size_t)sel * TE * KSPLIT
                                        + (size_t)(n0 + row) * KSPLIT + half * 32);
    uint32_t dOffA[4], dOffB[4];
#pragma unroll
    for (int i = 0; i < 4; i++) {
        uint32_t o = SW128((uint32_t)(row * 128 + half * 64 + i * 16));
        dOffA[i] = o;
        dOffB[i] = 16384u + o;
    }
    const uint32_t segA = 0x0010210u;   // [0,1,2,0,1,0]
    const uint32_t segB = 0x0211000u;   // [0,0,0,1,1,2]

#define ISSUE_STAGE(c_) do {                                                   \
    int _c = (c_);                                                             \
    int _seg = _c >> 4, _kc = _c & 15;                                         \
    int _pa = (segA >> (_seg * 4)) & 7, _pb = (segB >> (_seg * 4)) & 7;        \
    uint32_t _sb = smem_base + (_c % GEMM_STAGES) * GEMM_STAGE_BYTES;          \
    const char* _as = aG + (_pa * 1024 + _kc * 64) * 2;                        \
    const char* _bs = bG + (_pb * 1024 + _kc * 64) * 2;                        \
    _Pragma("unroll")                                                          \
    for (int _i = 0; _i < 4; _i++) {                                           \
        CP_ASYNC16(_sb + dOffA[_i], _as + _i * 16);                            \
        CP_ASYNC16(_sb + dOffB[_i], _bs + _i * 16);                            \
    }                                                                          \
    CP_COMMIT();                                                               \
} while (0)

    float acc[2][8][4];
#pragma unroll
    for (int i = 0; i < 2; i++)
#pragma unroll
        for (int j = 0; j < 8; j++)
#pragma unroll
            for (int k = 0; k < 4; k++) acc[i][j][k] = 0.f;

    const uint32_t lrow = lane & 15;
    const uint32_t lcol = (lane >> 4) * 16;

    ISSUE_STAGE(0);
    ISSUE_STAGE(1);

    for (int c = 0; c < NCHUNK; c++) {
        if (c < NCHUNK - 1) CP_WAIT1(); else CP_WAIT0();
        __syncthreads();
        if (c + 2 < NCHUNK) ISSUE_STAGE(c + 2);

        const uint32_t sb  = smem_base + (c % GEMM_STAGES) * GEMM_STAGE_BYTES;
        const uint32_t aRow = (uint32_t)(warp_m * 32) + lrow;
        const uint32_t bRow = (uint32_t)(warp_n * 64) + lrow;

#pragma unroll
        for (int kk = 0; kk < 4; kk++) {
            uint32_t a[2][4];
#pragma unroll
            for (int mt = 0; mt < 2; mt++) {
                uint32_t off = (aRow + mt * 16) * 128 + kk * 32 + lcol;
                LDSM_X4(a[mt][0], a[mt][1], a[mt][2], a[mt][3], sb + SW128(off));
            }
            uint32_t b[4][4];
#pragma unroll
            for (int nt2 = 0; nt2 < 4; nt2++) {
                uint32_t off = (bRow + nt2 * 16) * 128 + kk * 32 + lcol;
                LDSM_X4(b[nt2][0], b[nt2][1], b[nt2][2], b[nt2][3],
                        sb + 16384u + SW128(off));
            }
#pragma unroll
            for (int mt = 0; mt < 2; mt++)
#pragma unroll
                for (int nt2 = 0; nt2 < 4; nt2++) {
                    MMA_16816(acc[mt][nt2 * 2 + 0], a[mt], b[nt2][0], b[nt2][2]);
                    MMA_16816(acc[mt][nt2 * 2 + 1], a[mt], b[nt2][1], b[nt2][3]);
                }
        }
    }

    const int er = lane >> 2;
    const int ec = (lane & 3) * 2;
#pragma unroll
    for (int mt = 0; mt < 2; mt++) {
        const int r0 = m0 + warp_m * 32 + mt * 16 + er;
#pragma unroll
        for (int nt = 0; nt < 8; nt++) {
            const int col = n0 + warp_n * 64 + nt * 8 + ec;
            const float bx = bias[col], by = bias[col + 1];
            float* p = C + (size_t)r0 * TE + col;
            *(float2*)p            = make_float2(acc[mt][nt][0] + bx, acc[mt][nt][1] + by);
            *(float2*)(p + 8 * TE) = make_float2(acc[mt][nt][2] + bx, acc[mt][nt][3] + by);
        }
    }
#undef ISSUE_STAGE
}

// ---------------------------------------------------------------------------
// Attention-column kernel v6: HMMA scores + K-tile REGISTER prefetch.
// v5 issued cp.async for K then immediately CP_WAIT0'd it (zero overlap,
// 32 exposed L2 round trips per block). Now K(kt+1) is LDG'd right after the
// sync and consumed after the MMA+epilogue — latency hidden under tensor work.
// Arithmetic order identical to v5 => bit-identical results.
// ---------------------------------------------------------------------------
#define ES_STRIDE 514
#define OFF_QS  (64 * ES_STRIDE * 4)
#define OFF_KS  (OFF_QS + 3 * 8192)
#define OFF_COL (OFF_KS + 3 * 16384)
#define OFF_DEN (OFF_COL + 512 * 8)
#define OFF_INV (OFF_DEN + 128 * 8)
#define ATTN_SMEM (OFF_INV + 64 * 8)

__global__ __launch_bounds__(256) void attn_col_kernel()
{
    extern __shared__ char sm[];
    const uint32_t sb = smem_u32(sm);
    float*  Es     = (float*)sm;
    double* colacc = (double*)(sm + OFF_COL);
    double* den2   = (double*)(sm + OFF_DEN);    // [64][2]
    double* invd   = (double*)(sm + OFF_INV);    // [64]

    const int t = threadIdx.x, lane = t & 31, wid = t >> 5;
    const int wm = wid & 3, wn = wid >> 2;
    const int bh = blockIdx.x;

    const __nv_bfloat16* Qg = g_Qs2 + (size_t)bh * TS * 192;
    const __nv_bfloat16* Kg = g_Ks2 + (size_t)bh * TS * 192;

    colacc[t] = 0.0;
    colacc[t + 256] = 0.0;

    const uint32_t lrow = lane & 15;
    const uint32_t lcol = (lane >> 4) * 16;
    const int fr = lane >> 2;
    const int fc = (lane & 3) * 2;
    const int segAa[6] = {0, 1, 2, 0, 1, 0};
    const int segBa[6] = {0, 0, 0, 1, 1, 2};

    // K loader assignment: row = t>>1 (0..127), hf = t&1 (192B half of the row)
    const int krow = t >> 1;
    const int khf  = t & 1;
    const uint4* kGbase = (const uint4*)((const char*)(Kg) + (size_t)krow * 384 + khf * 192);
    // smem scatter offsets for the 12 16B units
    uint32_t kOff[12];
#pragma unroll
    for (int j = 0; j < 12; j++) {
        int i = khf * 12 + j;
        int seg = i >> 3, wi = (i & 7) * 16;
        kOff[j] = OFF_KS + seg * 16384 + SW128(krow * 128 + wi);
    }
    const size_t ktStride = 128 * 384 / 16;      // uint4 step between K tiles

    uint4 kreg[12];
    // prologue: prefetch K tile kt=0
#pragma unroll
    for (int j = 0; j < 12; j++) kreg[j] = kGbase[j];

    for (int qt = 0; qt < 8; qt++) {
        __syncthreads();   // colacc reads of prev Es done; Q/K smem free
        // Q tile via cp.async (waited at kt==0)
        {
            int row = t >> 2, qq = t & 3;
            const char* src = (const char*)(Qg + (size_t)(qt * 64 + row) * 192) + qq * 96;
#pragma unroll
            for (int j = 0; j < 6; j++) {
                int i = qq * 6 + j;
                int seg = i >> 3, wi = (i & 7) * 16;
                CP_ASYNC16(sb + OFF_QS + seg * 8192 + SW128(row * 128 + wi), src + j * 16);
            }
        }
        CP_COMMIT();
        if (t < 128) den2[t] = 0.0;

        for (int kt = 0; kt < 4; kt++) {
            // store prefetched K tile
#pragma unroll
            for (int j = 0; j < 12; j++)
                *(uint4*)(sm + (kOff[j] - 0)) = kreg[j];   // sm is char*; kOff absolute
            if (kt == 0) CP_WAIT0();                        // Q arrival
            __syncthreads();

            // prefetch next K tile (kt+1, or kt0 for next qt)
            if (kt < 3) {
#pragma unroll
                for (int j = 0; j < 12; j++) kreg[j] = kGbase[(kt + 1) * ktStride + j];
            } else if (qt < 7) {
#pragma unroll
                for (int j = 0; j < 12; j++) kreg[j] = kGbase[j];
            }

            float acc[8][4];
#pragma unroll
            for (int i = 0; i < 8; i++)
#pragma unroll
                for (int k = 0; k < 4; k++) acc[i][k] = 0.f;

#pragma unroll
            for (int ch = 0; ch < 6; ch++) {
                const uint32_t abase = sb + OFF_QS + segAa[ch] * 8192;
                const uint32_t bbase = sb + OFF_KS + segBa[ch] * 16384;
#pragma unroll
                for (int kk = 0; kk < 4; kk++) {
                    uint32_t a[4];
                    LDSM_X4(a[0], a[1], a[2], a[3],
                            abase + SW128((wm * 16 + lrow) * 128 + kk * 32 + lcol));
                    uint32_t b[4][4];
#pragma unroll
                    for (int nt2 = 0; nt2 < 4; nt2++)
                        LDSM_X4(b[nt2][0], b[nt2][1], b[nt2][2], b[nt2][3],
                                bbase + SW128((wn * 64 + nt2 * 16 + lrow) * 128 + kk * 32 + lcol));
#pragma unroll
                    for (int nt2 = 0; nt2 < 4; nt2++) {
                        MMA_16816(acc[nt2 * 2 + 0], a, b[nt2][0], b[nt2][2]);
                        MMA_16816(acc[nt2 * 2 + 1], a, b[nt2][1], b[nt2][3]);
                    }
                }
            }

            // epilogue: exp, Es stores, fp64 row sums
            const int r0 = wm * 16 + fr;
            double d0 = 0.0, d1 = 0.0;
#pragma unroll
            for (int nt = 0; nt < 8; nt++) {
                const int col = kt * 128 + wn * 64 + nt * 8 + fc;
                float e0 = fast_expf(fmaf(acc[nt][0], 0.125f, 1.0f));
                float e1 = fast_expf(fmaf(acc[nt][1], 0.125f, 1.0f));
                float e2 = fast_expf(fmaf(acc[nt][2], 0.125f, 1.0f));
                float e3 = fast_expf(fmaf(acc[nt][3], 0.125f, 1.0f));
                *(float2*)&Es[r0 * ES_STRIDE + col]       = make_float2(e0, e1);
                *(float2*)&Es[(r0 + 8) * ES_STRIDE + col] = make_float2(e2, e3);
                d0 += (double)e0 + (double)e1;
                d1 += (double)e2 + (double)e3;
            }
            d0 += __shfl_xor_sync(0xffffffffu, d0, 1);
            d0 += __shfl_xor_sync(0xffffffffu, d0, 2);
            d1 += __shfl_xor_sync(0xffffffffu, d1, 1);
            d1 += __shfl_xor_sync(0xffffffffu, d1, 2);
            if ((lane & 3) == 0) {
                den2[r0 * 2 + wn]       += d0;
                den2[(r0 + 8) * 2 + wn] += d1;
            }
            __syncthreads();   // MMA/epilogue done before next STS overwrites K
        }

        if (t < 64) invd[t] = 1.0 / (den2[t * 2] + den2[t * 2 + 1]);
        __syncthreads();

#pragma unroll
        for (int ss = 0; ss < 2; ss++) {
            int s = t + ss * 256;
            double a = colacc[s];
#pragma unroll 8
            for (int rr = 0; rr < 64; rr++)
                a = fma((double)Es[rr * ES_STRIDE + s], invd[rr], a);
            colacc[s] = a;
        }
    }

    g_colpart[(size_t)bh * TS + t]       = colacc[t];
    g_colpart[(size_t)bh * TS + t + 256] = colacc[t + 256];
}

// ---------------------------------------------------------------------------
// col -> log_softmax logits (fp64, deterministic tree reductions)
// ---------------------------------------------------------------------------
__global__ __launch_bounds__(512) void logits_kernel()
{
    __shared__ double red[512];
    const int b = blockIdx.x;
    const int s = threadIdx.x;

    double v = 0.0;
#pragma unroll
    for (int h = 0; h < TH; h++)
        v += g_colpart[((size_t)b * TH + h) * TS + s];

    red[s] = v;
    __syncthreads();
    for (int off = 256; off > 0; off >>= 1) {
        if (s < off) { double o = red[s + off]; if (o > red[s]) red[s] = o; }
        __syncthreads();
    }
    double m = red[0];
    __syncthreads();
    red[s] = exp(v - m);
    __syncthreads();
    for (int off = 256; off > 0; off >>= 1) {
        if (s < off) red[s] += red[s + off];
        __syncthreads();
    }
    double lse = m + log(red[0]);
    g_logits[(size_t)b * TS + s] = v - lse;
}

// ---------------------------------------------------------------------------
// Threefry-2x32 (JAX-exact, PARTITIONABLE): bits = o0 ^ o1, counter (0, i)
// ---------------------------------------------------------------------------
__device__ __forceinline__ void threefry2x32(
    unsigned k0, unsigned k1, unsigned x0, unsigned x1,
    unsigned& o0, unsigned& o1)
{
    const unsigned ks0 = k0, ks1 = k1, ks2 = k0 ^ k1 ^ 0x1BD11BDAu;
    x0 += ks0; x1 += ks1;
#define TF_RND(r) { x0 += x1; x1 = __funnelshift_l(x1, x1, r); x1 ^= x0; }
    TF_RND(13) TF_RND(15) TF_RND(26) TF_RND(6)   x0 += ks1; x1 += ks2 + 1u;
    TF_RND(17) TF_RND(29) TF_RND(16) TF_RND(24)  x0 += ks2; x1 += ks0 + 2u;
    TF_RND(13) TF_RND(15) TF_RND(26) TF_RND(6)   x0 += ks0; x1 += ks1 + 3u;
    TF_RND(17) TF_RND(29) TF_RND(16) TF_RND(24)  x0 += ks1; x1 += ks2 + 4u;
    TF_RND(13) TF_RND(15) TF_RND(26) TF_RND(6)   x0 += ks2; x1 += ks0 + 5u;
#undef TF_RND
    o0 = x0; o1 = x1;
}

// ---------------------------------------------------------------------------
// sample_kernel (validated R9): fp32 fast path + selective fp64 verification
// ---------------------------------------------------------------------------
__global__ __launch_bounds__(256) void sample_kernel(
    const float* __restrict__ tokens, float* __restrict__ out)
{
    const int warp = blockIdx.x * 8 + (threadIdx.x >> 5);   // 0..16383 = b*1024+j
    const int lane = threadIdx.x & 31;
    const int b = warp >> 10;
    const int j = warp & 1023;

    const double* lg = g_logits + (size_t)b * TS;

    float vreg[16];
    float best32 = -3.0e38f;
#pragma unroll
    for (int si = 0; si < 16; si++) {
        int s = lane + si * 32;
        unsigned i = (unsigned)warp * 512u + (unsigned)s;
        unsigned o0, o1;
        threefry2x32(0u, 42u, 0u, i, o0, o1);
        unsigned bits = o0 ^ o1;
        float f = __uint_as_float((bits >> 9) | 0x3f800000u) - 1.0f;
        float u = fmaxf(f, 1.17549435e-38f);
        float g32 = -logf(-logf(u));
        float v32 = g32 + (float)lg[s];
        vreg[si] = v32;
        best32 = fmaxf(best32, v32);
    }
#pragma unroll
    for (int off = 16; off > 0; off >>= 1)
        best32 = fmaxf(best32, __shfl_xor_sync(0xffffffffu, best32, off));

    const float thresh = best32 - 1.0e-4f;
    double best = -1.0e300;
    int    bi   = 0x7fffffff;
#pragma unroll
    for (int si = 0; si < 16; si++) {
        if (vreg[si] >= thresh) {
            int s = lane + si * 32;
            unsigned i = (unsigned)warp * 512u + (unsigned)s;
            unsigned o0, o1;
            threefry2x32(0u, 42u, 0u, i, o0, o1);
            unsigned bits = o0 ^ o1;
            float f = __uint_as_float((bits >> 9) | 0x3f800000u) - 1.0f;
            float u = fmaxf(f, 1.17549435e-38f);
            double g = -log(-log((double)u));        // EXACT round-3..12 formula
            double v = g + lg[s];
            if (v > best) { best = v; bi = s; }
        }
    }

#pragma unroll
    for (int off = 16; off > 0; off >>= 1) {
        double ov = __shfl_down_sync(0xffffffffu, best, off);
        int    oi = __shfl_down_sync(0xffffffffu, bi,   off);
        if (ov > best || (ov == best && oi < bi)) { best = ov; bi = oi; }
    }

    if (lane == 0)
        out[warp] = tokens[((size_t)b * TS + (size_t)bi) * TE + (size_t)j];
}

// ---------------------------------------------------------------------------
extern "C" void kernel_launch(void* const* d_in, const int* in_sizes, int n_in,
                              void* d_out, int out_size)
{
    (void)in_sizes; (void)n_in; (void)out_size;
    const float* tokens = (const float*)d_in[0];
    const float* Wq     = (const float*)d_in[1];
    const float* bq     = (const float*)d_in[2];
    const float* Wk     = (const float*)d_in[3];
    const float* bk     = (const float*)d_in[4];
    float* out = (float*)d_out;

    cudaFuncSetAttribute(gemm_hmma_kernel,
                         cudaFuncAttributeMaxDynamicSharedMemorySize, GEMM_SMEM);
    cudaFuncSetAttribute(attn_col_kernel,
                         cudaFuncAttributeMaxDynamicSharedMemorySize, ATTN_SMEM);

    split_inputs_kernel<<<10240, 256>>>(tokens, Wq, Wk);            // 0
    gemm_hmma_kernel<<<dim3(8, 64, 2), 256, GEMM_SMEM>>>(bq, bk);   // 1
    split_qk_kernel<<<dim3(8192, 1, 2), 256>>>();                   // 2
    attn_col_kernel<<<256, 256, ATTN_SMEM>>>();                     // 3 <- ncu capture
    logits_kernel<<<16, 512>>>();                                   // 4
    sample_kernel<<<2048, 256>>>(tokens, out);                      // 5
}

// round 14
// speedup vs baseline: 1.9431x; 1.9431x over previous
#include <cuda_runtime.h>
#include <cuda_bf16.h>
#include <math.h>
#include <stdint.h>

#define TB 16
#define TS 512
#define TE 1024
#define TH 16
#define TD 64
#define KSPLIT 3072          // 3 * TE (bf16 hi|mid|lo splits along K)

// Scratch (device globals: allocation-free rule)
static __device__ float  g_Q[(size_t)TB * TS * TE];
static __device__ float  g_K[(size_t)TB * TS * TE];
static __device__ double g_colpart[TB * TH * TS];
static __device__ double g_logits[TB * TS];
static __device__ __align__(128) __nv_bfloat16 g_As[(size_t)TB * TS * KSPLIT]; // tokens split
static __device__ __align__(128) __nv_bfloat16 g_Ws[(size_t)2 * TE * KSPLIT];  // Wq/Wk split
// per-head bf16 splits of Q/K: [bh][512 rows][3 segs x 64] (row = 192 bf16)
static __device__ __align__(128) __nv_bfloat16 g_Qs2[(size_t)TB * TH * TS * 192];
static __device__ __align__(128) __nv_bfloat16 g_Ks2[(size_t)TB * TH * TS * 192];

// ---------------------------------------------------------------------------
// PTX helpers (sm_80-class only: mma.sync / ldmatrix / cp.async — NO tcgen05)
// ---------------------------------------------------------------------------
__device__ __forceinline__ uint32_t smem_u32(const void* p) {
    uint32_t a;
    asm("{ .reg .u64 t; cvta.to.shared.u64 t, %1; cvt.u32.u64 %0, t; }" : "=r"(a) : "l"(p));
    return a;
}
#define SW128(o) ((o) ^ ((((uint32_t)(o)) >> 3) & 0x70u))

#define CP_ASYNC16(dst, src) \
    asm volatile("cp.async.cg.shared.global [%0], [%1], 16;" :: "r"(dst), "l"(src))
#define CP_COMMIT()  asm volatile("cp.async.commit_group;" ::: "memory")
#define CP_WAIT1()   asm volatile("cp.async.wait_group 1;" ::: "memory")
#define CP_WAIT0()   asm volatile("cp.async.wait_group 0;" ::: "memory")

#define LDSM_X4(r0, r1, r2, r3, a) \
    asm volatile("ldmatrix.sync.aligned.m8n8.x4.shared.b16 {%0,%1,%2,%3}, [%4];" \
                 : "=r"(r0), "=r"(r1), "=r"(r2), "=r"(r3) : "r"(a))

#define MMA_16816(D, A, B0, B1) \
    asm volatile("mma.sync.aligned.m16n8k16.row.col.f32.bf16.bf16.f32 " \
                 "{%0,%1,%2,%3}, {%4,%5,%6,%7}, {%8,%9}, {%0,%1,%2,%3};" \
                 : "+f"((D)[0]), "+f"((D)[1]), "+f"((D)[2]), "+f"((D)[3]) \
                 : "r"((A)[0]), "r"((A)[1]), "r"((A)[2]), "r"((A)[3]), \
                   "r"(B0), "r"(B1))

// ---------------------------------------------------------------------------
// Deterministic FMA-pipe exp
// ---------------------------------------------------------------------------
__device__ __forceinline__ float fast_expf(float x) {
    const float LOG2E   = 1.4426950408889634f;
    const float LN2_HI  = 0.693145751953125f;
    const float LN2_LO  = 1.428606765330187e-06f;
    float y  = x * LOG2E;
    float r  = rintf(y);
    int   ri = (int)r;
    float t  = fmaf(-r, LN2_HI, x);
    t = fmaf(-r, LN2_LO, t);
    float p = 1.9841269841e-4f;
    p = fmaf(p, t, 1.3888888889e-3f);
    p = fmaf(p, t, 8.3333333333e-3f);
    p = fmaf(p, t, 4.1666666667e-2f);
    p = fmaf(p, t, 1.6666666667e-1f);
    p = fmaf(p, t, 0.5f);
    p = fmaf(p, t, 1.0f);
    p = fmaf(p, t, 1.0f);
    return p * __int_as_float((ri + 127) << 23);
}

// ---------------------------------------------------------------------------
// Exact 3-way bf16 split
// ---------------------------------------------------------------------------
__device__ __forceinline__ void split3(float x, unsigned short& h, unsigned short& m,
                                       unsigned short& l) {
    __nv_bfloat16 bh = __float2bfloat16_rn(x);
    float r  = x - __bfloat162float(bh);
    __nv_bfloat16 bm = __float2bfloat16_rn(r);
    float r2 = r - __bfloat162float(bm);
    __nv_bfloat16 bl = __float2bfloat16_rn(r2);
    h = __bfloat16_as_ushort(bh);
    m = __bfloat16_as_ushort(bm);
    l = __bfloat16_as_ushort(bl);
}

__device__ __forceinline__ void split_store4s(const float4 v, __nv_bfloat16* dst, int stride) {
    unsigned short h[4], m[4], l[4];
    split3(v.x, h[0], m[0], l[0]);
    split3(v.y, h[1], m[1], l[1]);
    split3(v.z, h[2], m[2], l[2]);
    split3(v.w, h[3], m[3], l[3]);
    uint2 uh = make_uint2((uint32_t)h[0] | ((uint32_t)h[1] << 16),
                          (uint32_t)h[2] | ((uint32_t)h[3] << 16));
    uint2 um = make_uint2((uint32_t)m[0] | ((uint32_t)m[1] << 16),
                          (uint32_t)m[2] | ((uint32_t)m[3] << 16));
    uint2 ul = make_uint2((uint32_t)l[0] | ((uint32_t)l[1] << 16),
                          (uint32_t)l[2] | ((uint32_t)l[3] << 16));
    *(uint2*)(dst)              = uh;
    *(uint2*)(dst + stride)     = um;
    *(uint2*)(dst + 2 * stride) = ul;
}

// fused input split: blocks [0,8192) tokens -> g_As; [8192,9216) Wq; [9216,10240) Wk
__global__ __launch_bounds__(256) void split_inputs_kernel(
    const float* __restrict__ tokens,
    const float* __restrict__ Wq, const float* __restrict__ Wk)
{
    int blk = blockIdx.x;
    if (blk < 8192) {
        size_t i = (size_t)blk * 256 + threadIdx.x;
        float4 v = ((const float4*)tokens)[i];
        size_t row = i >> 8;
        int    c4  = (int)(i & 255) * 4;
        split_store4s(v, g_As + row * KSPLIT + c4, TE);
    } else {
        int sel = (blk >= 9216) ? 1 : 0;
        size_t i = (size_t)(blk - 8192 - sel * 1024) * 256 + threadIdx.x;
        const float* W = sel ? Wk : Wq;
        float4 v = ((const float4*)W)[i];
        size_t row = i >> 8;
        int    c4  = (int)(i & 255) * 4;
        split_store4s(v, g_Ws + (size_t)sel * TE * KSPLIT + row * KSPLIT + c4, TE);
    }
}

// g_Q/g_K fp32 [8192,1024] -> per-head split [bh][512][3*64] bf16
__global__ __launch_bounds__(256) void split_qk_kernel()
{
    const float*    src = blockIdx.z ? g_K : g_Q;
    __nv_bfloat16*  dst = blockIdx.z ? g_Ks2 : g_Qs2;
    size_t i = (size_t)blockIdx.x * 256 + threadIdx.x;
    float4 v = ((const float4*)src)[i];
    size_t r = i >> 8;
    int    c4 = (int)(i & 255) * 4;
    int h = c4 >> 6, d = c4 & 63;
    int b = (int)(r >> 9), s = (int)(r & 511);
    __nv_bfloat16* o = dst + (((size_t)(b * TH + h) * TS + s) * 192 + d);
    split_store4s(v, o, 64);
}

// ---------------------------------------------------------------------------
// HMMA GEMM: 3-term bf16-split product (hh + hm + mh).
// Dropped mm/hl/lh terms are ~2^-17..2^-18 relative -> score error ~3e-5 ->
// logit error ~6e-7 after softmax/averaging (expected argmax flips ~0.02).
// NCHUNK halves 96 -> 48: tensor work and smem traffic both halve.
// ---------------------------------------------------------------------------
#define GEMM_STAGES 3
#define GEMM_STAGE_BYTES 32768
#define GEMM_SMEM (GEMM_STAGES * GEMM_STAGE_BYTES)
#define NCHUNK 48                              // 3 segs * 16 chunks of k64

__global__ __launch_bounds__(256) void gemm_hmma_kernel(const float* __restrict__ bq,
                                                        const float* __restrict__ bk)
{
    extern __shared__ char dsm[];
    const uint32_t smem_base = smem_u32(dsm);

    const int t    = threadIdx.x;
    const int lane = t & 31, wid = t >> 5;
    const int warp_m = wid & 3;
    const int warp_n = wid >> 2;
    const int sel = blockIdx.z;
    const int m0  = blockIdx.y * 128;
    const int n0  = blockIdx.x * 128;

    float*       C    = sel ? g_K : g_Q;
    const float* bias = sel ? bk : bq;

    const int row  = t >> 1;
    const int half = t & 1;
    const char* aG = (const char*)(g_As + (size_t)(m0 + row) * KSPLIT + half * 32);
    const char* bG = (const char*)(g_Ws + (size_t)sel * TE * KSPLIT
                                        + (size_t)(n0 + row) * KSPLIT + half * 32);
    uint32_t dOffA[4], dOffB[4];
#pragma unroll
    for (int i = 0; i < 4; i++) {
        uint32_t o = SW128((uint32_t)(row * 128 + half * 64 + i * 16));
        dOffA[i] = o;
        dOffB[i] = 16384u + o;
    }
    const uint32_t segA = 0x100u;   // [0,0,1]  (hh, hm, mh) — seg s in nibble s
    const uint32_t segB = 0x010u;   // [0,1,0]

#define ISSUE_STAGE(c_) do {                                                   \
    int _c = (c_);                                                             \
    int _seg = _c >> 4, _kc = _c & 15;                                         \
    int _pa = (segA >> (_seg * 4)) & 7, _pb = (segB >> (_seg * 4)) & 7;        \
    uint32_t _sb = smem_base + (_c % GEMM_STAGES) * GEMM_STAGE_BYTES;          \
    const char* _as = aG + (_pa * 1024 + _kc * 64) * 2;                        \
    const char* _bs = bG + (_pb * 1024 + _kc * 64) * 2;                        \
    _Pragma("unroll")                                                          \
    for (int _i = 0; _i < 4; _i++) {                                           \
        CP_ASYNC16(_sb + dOffA[_i], _as + _i * 16);                            \
        CP_ASYNC16(_sb + dOffB[_i], _bs + _i * 16);                            \
    }                                                                          \
    CP_COMMIT();                                                               \
} while (0)

    float acc[2][8][4];
#pragma unroll
    for (int i = 0; i < 2; i++)
#pragma unroll
        for (int j = 0; j < 8; j++)
#pragma unroll
            for (int k = 0; k < 4; k++) acc[i][j][k] = 0.f;

    const uint32_t lrow = lane & 15;
    const uint32_t lcol = (lane >> 4) * 16;

    ISSUE_STAGE(0);
    ISSUE_STAGE(1);

    for (int c = 0; c < NCHUNK; c++) {
        if (c < NCHUNK - 1) CP_WAIT1(); else CP_WAIT0();
        __syncthreads();
        if (c + 2 < NCHUNK) ISSUE_STAGE(c + 2);

        const uint32_t sb  = smem_base + (c % GEMM_STAGES) * GEMM_STAGE_BYTES;
        const uint32_t aRow = (uint32_t)(warp_m * 32) + lrow;
        const uint32_t bRow = (uint32_t)(warp_n * 64) + lrow;

#pragma unroll
        for (int kk = 0; kk < 4; kk++) {
            uint32_t a[2][4];
#pragma unroll
            for (int mt = 0; mt < 2; mt++) {
                uint32_t off = (aRow + mt * 16) * 128 + kk * 32 + lcol;
                LDSM_X4(a[mt][0], a[mt][1], a[mt][2], a[mt][3], sb + SW128(off));
            }
            uint32_t b[4][4];
#pragma unroll
            for (int nt2 = 0; nt2 < 4; nt2++) {
                uint32_t off = (bRow + nt2 * 16) * 128 + kk * 32 + lcol;
                LDSM_X4(b[nt2][0], b[nt2][1], b[nt2][2], b[nt2][3],
                        sb + 16384u + SW128(off));
            }
#pragma unroll
            for (int mt = 0; mt < 2; mt++)
#pragma unroll
                for (int nt2 = 0; nt2 < 4; nt2++) {
                    MMA_16816(acc[mt][nt2 * 2 + 0], a[mt], b[nt2][0], b[nt2][2]);
                    MMA_16816(acc[mt][nt2 * 2 + 1], a[mt], b[nt2][1], b[nt2][3]);
                }
        }
    }

    const int er = lane >> 2;
    const int ec = (lane & 3) * 2;
#pragma unroll
    for (int mt = 0; mt < 2; mt++) {
        const int r0 = m0 + warp_m * 32 + mt * 16 + er;
#pragma unroll
        for (int nt = 0; nt < 8; nt++) {
            const int col = n0 + warp_n * 64 + nt * 8 + ec;
            const float bx = bias[col], by = bias[col + 1];
            float* p = C + (size_t)r0 * TE + col;
            *(float2*)p            = make_float2(acc[mt][nt][0] + bx, acc[mt][nt][1] + by);
            *(float2*)(p + 8 * TE) = make_float2(acc[mt][nt][2] + bx, acc[mt][nt][3] + by);
        }
    }
#undef ISSUE_STAGE
}

// ---------------------------------------------------------------------------
// Attention-column kernel v5 (EXACT revert of the R12 version — v6's LDG
// prefetch blew registers to 225 and regressed 500us).
// ---------------------------------------------------------------------------
#define ES_STRIDE 514
#define OFF_QS  (64 * ES_STRIDE * 4)
#define OFF_KS  (OFF_QS + 3 * 8192)
#define OFF_COL (OFF_KS + 3 * 16384)
#define OFF_DEN (OFF_COL + 512 * 8)
#define OFF_INV (OFF_DEN + 128 * 8)
#define ATTN_SMEM (OFF_INV + 64 * 8)

__global__ __launch_bounds__(256) void attn_col_kernel()
{
    extern __shared__ char sm[];
    const uint32_t sb = smem_u32(sm);
    float*  Es     = (float*)sm;
    double* colacc = (double*)(sm + OFF_COL);
    double* den2   = (double*)(sm + OFF_DEN);    // [64][2]
    double* invd   = (double*)(sm + OFF_INV);    // [64]

    const int t = threadIdx.x, lane = t & 31, wid = t >> 5;
    const int wm = wid & 3, wn = wid >> 2;
    const int bh = blockIdx.x;

    const __nv_bfloat16* Qg = g_Qs2 + (size_t)bh * TS * 192;
    const __nv_bfloat16* Kg = g_Ks2 + (size_t)bh * TS * 192;

    colacc[t] = 0.0;
    colacc[t + 256] = 0.0;

    const uint32_t lrow = lane & 15;
    const uint32_t lcol = (lane >> 4) * 16;
    const int fr = lane >> 2;
    const int fc = (lane & 3) * 2;
    const int segAa[6] = {0, 1, 2, 0, 1, 0};
    const int segBa[6] = {0, 0, 0, 1, 1, 2};

    for (int qt = 0; qt < 8; qt++) {
        __syncthreads();
        {
            int row = t >> 2, qq = t & 3;
            const char* src = (const char*)(Qg + (size_t)(qt * 64 + row) * 192) + qq * 96;
#pragma unroll
            for (int j = 0; j < 6; j++) {
                int i = qq * 6 + j;
                int seg = i >> 3, wi = (i & 7) * 16;
                CP_ASYNC16(sb + OFF_QS + seg * 8192 + SW128(row * 128 + wi), src + j * 16);
            }
        }
        CP_COMMIT();
        if (t < 128) den2[t] = 0.0;

        for (int kt = 0; kt < 4; kt++) {
            __syncthreads();
            {
                int row = t >> 1, hf = t & 1;
                const char* src = (const char*)(Kg + (size_t)(kt * 128 + row) * 192) + hf * 192;
#pragma unroll
                for (int j = 0; j < 12; j++) {
                    int i = hf * 12 + j;
                    int seg = i >> 3, wi = (i & 7) * 16;
                    CP_ASYNC16(sb + OFF_KS + seg * 16384 + SW128(row * 128 + wi), src + j * 16);
                }
            }
            CP_COMMIT();
            CP_WAIT0();
            __syncthreads();

            float acc[8][4];
#pragma unroll
            for (int i = 0; i < 8; i++)
#pragma unroll
                for (int k = 0; k < 4; k++) acc[i][k] = 0.f;

#pragma unroll
            for (int ch = 0; ch < 6; ch++) {
                const uint32_t abase = sb + OFF_QS + segAa[ch] * 8192;
                const uint32_t bbase = sb + OFF_KS + segBa[ch] * 16384;
#pragma unroll
                for (int kk = 0; kk < 4; kk++) {
                    uint32_t a[4];
                    LDSM_X4(a[0], a[1], a[2], a[3],
                            abase + SW128((wm * 16 + lrow) * 128 + kk * 32 + lcol));
                    uint32_t b[4][4];
#pragma unroll
                    for (int nt2 = 0; nt2 < 4; nt2++)
                        LDSM_X4(b[nt2][0], b[nt2][1], b[nt2][2], b[nt2][3],
                                bbase + SW128((wn * 64 + nt2 * 16 + lrow) * 128 + kk * 32 + lcol));
#pragma unroll
                    for (int nt2 = 0; nt2 < 4; nt2++) {
                        MMA_16816(acc[nt2 * 2 + 0], a, b[nt2][0], b[nt2][2]);
                        MMA_16816(acc[nt2 * 2 + 1], a, b[nt2][1], b[nt2][3]);
                    }
                }
            }

            const int r0 = wm * 16 + fr;
            double d0 = 0.0, d1 = 0.0;
#pragma unroll
            for (int nt = 0; nt < 8; nt++) {
                const int col = kt * 128 + wn * 64 + nt * 8 + fc;
                float e0 = fast_expf(fmaf(acc[nt][0], 0.125f, 1.0f));
                float e1 = fast_expf(fmaf(acc[nt][1], 0.125f, 1.0f));
                float e2 = fast_expf(fmaf(acc[nt][2], 0.125f, 1.0f));
                float e3 = fast_expf(fmaf(acc[nt][3], 0.125f, 1.0f));
                *(float2*)&Es[r0 * ES_STRIDE + col]       = make_float2(e0, e1);
                *(float2*)&Es[(r0 + 8) * ES_STRIDE + col] = make_float2(e2, e3);
                d0 += (double)e0 + (double)e1;
                d1 += (double)e2 + (double)e3;
            }
            d0 += __shfl_xor_sync(0xffffffffu, d0, 1);
            d0 += __shfl_xor_sync(0xffffffffu, d0, 2);
            d1 += __shfl_xor_sync(0xffffffffu, d1, 1);
            d1 += __shfl_xor_sync(0xffffffffu, d1, 2);
            if ((lane & 3) == 0) {
                den2[r0 * 2 + wn]       += d0;
                den2[(r0 + 8) * 2 + wn] += d1;
            }
        }

        __syncthreads();
        if (t < 64) invd[t] = 1.0 / (den2[t * 2] + den2[t * 2 + 1]);
        __syncthreads();

#pragma unroll
        for (int ss = 0; ss < 2; ss++) {
            int s = t + ss * 256;
            double a = colacc[s];
#pragma unroll 8
            for (int rr = 0; rr < 64; rr++)
                a = fma((double)Es[rr * ES_STRIDE + s], invd[rr], a);
            colacc[s] = a;
        }
    }

    g_colpart[(size_t)bh * TS + t]       = colacc[t];
    g_colpart[(size_t)bh * TS + t + 256] = colacc[t + 256];
}

// ---------------------------------------------------------------------------
// col -> log_softmax logits (fp64, deterministic tree reductions)
// ---------------------------------------------------------------------------
__global__ __launch_bounds__(512) void logits_kernel()
{
    __shared__ double red[512];
    const int b = blockIdx.x;
    const int s = threadIdx.x;

    double v = 0.0;
#pragma unroll
    for (int h = 0; h < TH; h++)
        v += g_colpart[((size_t)b * TH + h) * TS + s];

    red[s] = v;
    __syncthreads();
    for (int off = 256; off > 0; off >>= 1) {
        if (s < off) { double o = red[s + off]; if (o > red[s]) red[s] = o; }
        __syncthreads();
    }
    double m = red[0];
    __syncthreads();
    red[s] = exp(v - m);
    __syncthreads();
    for (int off = 256; off > 0; off >>= 1) {
        if (s < off) red[s] += red[s + off];
        __syncthreads();
    }
    double lse = m + log(red[0]);
    g_logits[(size_t)b * TS + s] = v - lse;
}

// ---------------------------------------------------------------------------
// Threefry-2x32 (JAX-exact, PARTITIONABLE): bits = o0 ^ o1, counter (0, i)
// ---------------------------------------------------------------------------
__device__ __forceinline__ void threefry2x32(
    unsigned k0, unsigned k1, unsigned x0, unsigned x1,
    unsigned& o0, unsigned& o1)
{
    const unsigned ks0 = k0, ks1 = k1, ks2 = k0 ^ k1 ^ 0x1BD11BDAu;
    x0 += ks0; x1 += ks1;
#define TF_RND(r) { x0 += x1; x1 = __funnelshift_l(x1, x1, r); x1 ^= x0; }
    TF_RND(13) TF_RND(15) TF_RND(26) TF_RND(6)   x0 += ks1; x1 += ks2 + 1u;
    TF_RND(17) TF_RND(29) TF_RND(16) TF_RND(24)  x0 += ks2; x1 += ks0 + 2u;
    TF_RND(13) TF_RND(15) TF_RND(26) TF_RND(6)   x0 += ks0; x1 += ks1 + 3u;
    TF_RND(17) TF_RND(29) TF_RND(16) TF_RND(24)  x0 += ks1; x1 += ks2 + 4u;
    TF_RND(13) TF_RND(15) TF_RND(26) TF_RND(6)   x0 += ks2; x1 += ks0 + 5u;
#undef TF_RND
    o0 = x0; o1 = x1;
}

// ---------------------------------------------------------------------------
// sample_kernel (validated R9): fp32 fast path + selective fp64 verification
// ---------------------------------------------------------------------------
__global__ __launch_bounds__(256) void sample_kernel(
    const float* __restrict__ tokens, float* __restrict__ out)
{
    const int warp = blockIdx.x * 8 + (threadIdx.x >> 5);   // 0..16383 = b*1024+j
    const int lane = threadIdx.x & 31;
    const int b = warp >> 10;
    const int j = warp & 1023;

    const double* lg = g_logits + (size_t)b * TS;

    float vreg[16];
    float best32 = -3.0e38f;
#pragma unroll
    for (int si = 0; si < 16; si++) {
        int s = lane + si * 32;
        unsigned i = (unsigned)warp * 512u + (unsigned)s;
        unsigned o0, o1;
        threefry2x32(0u, 42u, 0u, i, o0, o1);
        unsigned bits = o0 ^ o1;
        float f = __uint_as_float((bits >> 9) | 0x3f800000u) - 1.0f;
        float u = fmaxf(f, 1.17549435e-38f);
        float g32 = -logf(-logf(u));
        float v32 = g32 + (float)lg[s];
        vreg[si] = v32;
        best32 = fmaxf(best32, v32);
    }
#pragma unroll
    for (int off = 16; off > 0; off >>= 1)
        best32 = fmaxf(best32, __shfl_xor_sync(0xffffffffu, best32, off));

    const float thresh = best32 - 1.0e-4f;
    double best = -1.0e300;
    int    bi   = 0x7fffffff;
#pragma unroll
    for (int si = 0; si < 16; si++) {
        if (vreg[si] >= thresh) {
            int s = lane + si * 32;
            unsigned i = (unsigned)warp * 512u + (unsigned)s;
            unsigned o0, o1;
            threefry2x32(0u, 42u, 0u, i, o0, o1);
            unsigned bits = o0 ^ o1;
            float f = __uint_as_float((bits >> 9) | 0x3f800000u) - 1.0f;
            float u = fmaxf(f, 1.17549435e-38f);
            double g = -log(-log((double)u));
            double v = g + lg[s];
            if (v > best) { best = v; bi = s; }
        }
    }

#pragma unroll
    for (int off = 16; off > 0; off >>= 1) {
        double ov = __shfl_down_sync(0xffffffffu, best, off);
        int    oi = __shfl_down_sync(0xffffffffu, bi,   off);
        if (ov > best || (ov == best && oi < bi)) { best = ov; bi = oi; }
    }

    if (lane == 0)
        out[warp] = tokens[((size_t)b * TS + (size_t)bi) * TE + (size_t)j];
}

// ---------------------------------------------------------------------------
extern "C" void kernel_launch(void* const* d_in, const int* in_sizes, int n_in,
                              void* d_out, int out_size)
{
    (void)in_sizes; (void)n_in; (void)out_size;
    const float* tokens = (const float*)d_in[0];
    const float* Wq     = (const float*)d_in[1];
    const float* bq     = (const float*)d_in[2];
    const float* Wk     = (const float*)d_in[3];
    const float* bk     = (const float*)d_in[4];
    float* out = (float*)d_out;

    cudaFuncSetAttribute(gemm_hmma_kernel,
                         cudaFuncAttributeMaxDynamicSharedMemorySize, GEMM_SMEM);
    cudaFuncSetAttribute(attn_col_kernel,
                         cudaFuncAttributeMaxDynamicSharedMemorySize, ATTN_SMEM);

    split_inputs_kernel<<<10240, 256>>>(tokens, Wq, Wk);            // 0
    gemm_hmma_kernel<<<dim3(8, 64, 2), 256, GEMM_SMEM>>>(bq, bk);   // 1
    split_qk_kernel<<<dim3(8192, 1, 2), 256>>>();                   // 2
    attn_col_kernel<<<256, 256, ATTN_SMEM>>>();                     // 3 <- ncu capture
    logits_kernel<<<16, 512>>>();                                   // 4
    sample_kernel<<<2048, 256>>>(tokens, out);                      // 5
}

// round 15
// speedup vs baseline: 2.2140x; 1.1394x over previous
#include <cuda_runtime.h>
#include <cuda_bf16.h>
#include <cuda_fp16.h>
#include <math.h>
#include <stdint.h>

#define TB 16
#define TS 512
#define TE 1024
#define TH 16
#define TD 64
#define KSPLIT 3072          // 3 * TE (bf16 hi|mid|lo splits along K)

// Scratch (device globals: allocation-free rule)
static __device__ float  g_Q[(size_t)TB * TS * TE];
static __device__ float  g_K[(size_t)TB * TS * TE];
static __device__ double g_colpart[TB * TH * TS];
static __device__ double g_logits[TB * TS];
static __device__ __align__(128) __nv_bfloat16 g_As[(size_t)TB * TS * KSPLIT]; // tokens split
static __device__ __align__(128) __nv_bfloat16 g_Ws[(size_t)2 * TE * KSPLIT];  // Wq/Wk split
// per-head bf16 splits of Q/K: [bh][512 rows][3 segs x 64] (row = 192 bf16)
static __device__ __align__(128) __nv_bfloat16 g_Qs2[(size_t)TB * TH * TS * 192];
static __device__ __align__(128) __nv_bfloat16 g_Ks2[(size_t)TB * TH * TS * 192];

// ---------------------------------------------------------------------------
// PTX helpers (sm_80-class only: mma.sync / ldmatrix / cp.async — NO tcgen05)
// ---------------------------------------------------------------------------
__device__ __forceinline__ uint32_t smem_u32(const void* p) {
    uint32_t a;
    asm("{ .reg .u64 t; cvta.to.shared.u64 t, %1; cvt.u32.u64 %0, t; }" : "=r"(a) : "l"(p));
    return a;
}
#define SW128(o) ((o) ^ ((((uint32_t)(o)) >> 3) & 0x70u))

#define CP_ASYNC16(dst, src) \
    asm volatile("cp.async.cg.shared.global [%0], [%1], 16;" :: "r"(dst), "l"(src))
#define CP_COMMIT()  asm volatile("cp.async.commit_group;" ::: "memory")
#define CP_WAIT1()   asm volatile("cp.async.wait_group 1;" ::: "memory")
#define CP_WAIT0()   asm volatile("cp.async.wait_group 0;" ::: "memory")

#define LDSM_X4(r0, r1, r2, r3, a) \
    asm volatile("ldmatrix.sync.aligned.m8n8.x4.shared.b16 {%0,%1,%2,%3}, [%4];" \
                 : "=r"(r0), "=r"(r1), "=r"(r2), "=r"(r3) : "r"(a))

#define MMA_16816(D, A, B0, B1) \
    asm volatile("mma.sync.aligned.m16n8k16.row.col.f32.bf16.bf16.f32 " \
                 "{%0,%1,%2,%3}, {%4,%5,%6,%7}, {%8,%9}, {%0,%1,%2,%3};" \
                 : "+f"((D)[0]), "+f"((D)[1]), "+f"((D)[2]), "+f"((D)[3]) \
                 : "r"((A)[0]), "r"((A)[1]), "r"((A)[2]), "r"((A)[3]), \
                   "r"(B0), "r"(B1))

// ---------------------------------------------------------------------------
// Deterministic FMA-pipe exp
// ---------------------------------------------------------------------------
__device__ __forceinline__ float fast_expf(float x) {
    const float LOG2E   = 1.4426950408889634f;
    const float LN2_HI  = 0.693145751953125f;
    const float LN2_LO  = 1.428606765330187e-06f;
    float y  = x * LOG2E;
    float r  = rintf(y);
    int   ri = (int)r;
    float t  = fmaf(-r, LN2_HI, x);
    t = fmaf(-r, LN2_LO, t);
    float p = 1.9841269841e-4f;
    p = fmaf(p, t, 1.3888888889e-3f);
    p = fmaf(p, t, 8.3333333333e-3f);
    p = fmaf(p, t, 4.1666666667e-2f);
    p = fmaf(p, t, 1.6666666667e-1f);
    p = fmaf(p, t, 0.5f);
    p = fmaf(p, t, 1.0f);
    p = fmaf(p, t, 1.0f);
    return p * __int_as_float((ri + 127) << 23);
}

// ---------------------------------------------------------------------------
// Exact 3-way bf16 split
// ---------------------------------------------------------------------------
__device__ __forceinline__ void split3(float x, unsigned short& h, unsigned short& m,
                                       unsigned short& l) {
    __nv_bfloat16 bh = __float2bfloat16_rn(x);
    float r  = x - __bfloat162float(bh);
    __nv_bfloat16 bm = __float2bfloat16_rn(r);
    float r2 = r - __bfloat162float(bm);
    __nv_bfloat16 bl = __float2bfloat16_rn(r2);
    h = __bfloat16_as_ushort(bh);
    m = __bfloat16_as_ushort(bm);
    l = __bfloat16_as_ushort(bl);
}

__device__ __forceinline__ void split_store4s(const float4 v, __nv_bfloat16* dst, int stride) {
    unsigned short h[4], m[4], l[4];
    split3(v.x, h[0], m[0], l[0]);
    split3(v.y, h[1], m[1], l[1]);
    split3(v.z, h[2], m[2], l[2]);
    split3(v.w, h[3], m[3], l[3]);
    uint2 uh = make_uint2((uint32_t)h[0] | ((uint32_t)h[1] << 16),
                          (uint32_t)h[2] | ((uint32_t)h[3] << 16));
    uint2 um = make_uint2((uint32_t)m[0] | ((uint32_t)m[1] << 16),
                          (uint32_t)m[2] | ((uint32_t)m[3] << 16));
    uint2 ul = make_uint2((uint32_t)l[0] | ((uint32_t)l[1] << 16),
                          (uint32_t)l[2] | ((uint32_t)l[3] << 16));
    *(uint2*)(dst)              = uh;
    *(uint2*)(dst + stride)     = um;
    *(uint2*)(dst + 2 * stride) = ul;
}

// fused input split: blocks [0,8192) tokens -> g_As; [8192,9216) Wq; [9216,10240) Wk
__global__ __launch_bounds__(256) void split_inputs_kernel(
    const float* __restrict__ tokens,
    const float* __restrict__ Wq, const float* __restrict__ Wk)
{
    int blk = blockIdx.x;
    if (blk < 8192) {
        size_t i = (size_t)blk * 256 + threadIdx.x;
        float4 v = ((const float4*)tokens)[i];
        size_t row = i >> 8;
        int    c4  = (int)(i & 255) * 4;
        split_store4s(v, g_As + row * KSPLIT + c4, TE);
    } else {
        int sel = (blk >= 9216) ? 1 : 0;
        size_t i = (size_t)(blk - 8192 - sel * 1024) * 256 + threadIdx.x;
        const float* W = sel ? Wk : Wq;
        float4 v = ((const float4*)W)[i];
        size_t row = i >> 8;
        int    c4  = (int)(i & 255) * 4;
        split_store4s(v, g_Ws + (size_t)sel * TE * KSPLIT + row * KSPLIT + c4, TE);
    }
}

// g_Q/g_K fp32 [8192,1024] -> per-head split [bh][512][3*64] bf16
__global__ __launch_bounds__(256) void split_qk_kernel()
{
    const float*    src = blockIdx.z ? g_K : g_Q;
    __nv_bfloat16*  dst = blockIdx.z ? g_Ks2 : g_Qs2;
    size_t i = (size_t)blockIdx.x * 256 + threadIdx.x;
    float4 v = ((const float4*)src)[i];
    size_t r = i >> 8;
    int    c4 = (int)(i & 255) * 4;
    int h = c4 >> 6, d = c4 & 63;
    int b = (int)(r >> 9), s = (int)(r & 511);
    __nv_bfloat16* o = dst + (((size_t)(b * TH + h) * TS + s) * 192 + d);
    split_store4s(v, o, 64);
}

// ---------------------------------------------------------------------------
// HMMA GEMM: 3-term bf16-split product (hh + hm + mh) — validated R14.
// ---------------------------------------------------------------------------
#define GEMM_STAGES 3
#define GEMM_STAGE_BYTES 32768
#define GEMM_SMEM (GEMM_STAGES * GEMM_STAGE_BYTES)
#define NCHUNK 48

__global__ __launch_bounds__(256) void gemm_hmma_kernel(const float* __restrict__ bq,
                                                        const float* __restrict__ bk)
{
    extern __shared__ char dsm[];
    const uint32_t smem_base = smem_u32(dsm);

    const int t    = threadIdx.x;
    const int lane = t & 31, wid = t >> 5;
    const int warp_m = wid & 3;
    const int warp_n = wid >> 2;
    const int sel = blockIdx.z;
    const int m0  = blockIdx.y * 128;
    const int n0  = blockIdx.x * 128;

    float*       C    = sel ? g_K : g_Q;
    const float* bias = sel ? bk : bq;

    const int row  = t >> 1;
    const int half = t & 1;
    const char* aG = (const char*)(g_As + (size_t)(m0 + row) * KSPLIT + half * 32);
    const char* bG = (const char*)(g_Ws + (size_t)sel * TE * KSPLIT
                                        + (size_t)(n0 + row) * KSPLIT + half * 32);
    uint32_t dOffA[4], dOffB[4];
#pragma unroll
    for (int i = 0; i < 4; i++) {
        uint32_t o = SW128((uint32_t)(row * 128 + half * 64 + i * 16));
        dOffA[i] = o;
        dOffB[i] = 16384u + o;
    }
    const uint32_t segA = 0x100u;   // [0,0,1]
    const uint32_t segB = 0x010u;   // [0,1,0]

#define ISSUE_STAGE(c_) do {                                                   \
    int _c = (c_);                                                             \
    int _seg = _c >> 4, _kc = _c & 15;                                         \
    int _pa = (segA >> (_seg * 4)) & 7, _pb = (segB >> (_seg * 4)) & 7;        \
    uint32_t _sb = smem_base + (_c % GEMM_STAGES) * GEMM_STAGE_BYTES;          \
    const char* _as = aG + (_pa * 1024 + _kc * 64) * 2;                        \
    const char* _bs = bG + (_pb * 1024 + _kc * 64) * 2;                        \
    _Pragma("unroll")                                                          \
    for (int _i = 0; _i < 4; _i++) {                                           \
        CP_ASYNC16(_sb + dOffA[_i], _as + _i * 16);                            \
        CP_ASYNC16(_sb + dOffB[_i], _bs + _i * 16);                            \
    }                                                                          \
    CP_COMMIT();                                                               \
} while (0)

    float acc[2][8][4];
#pragma unroll
    for (int i = 0; i < 2; i++)
#pragma unroll
        for (int j = 0; j < 8; j++)
#pragma unroll
            for (int k = 0; k < 4; k++) acc[i][j][k] = 0.f;

    const uint32_t lrow = lane & 15;
    const uint32_t lcol = (lane >> 4) * 16;

    ISSUE_STAGE(0);
    ISSUE_STAGE(1);

    for (int c = 0; c < NCHUNK; c++) {
        if (c < NCHUNK - 1) CP_WAIT1(); else CP_WAIT0();
        __syncthreads();
        if (c + 2 < NCHUNK) ISSUE_STAGE(c + 2);

        const uint32_t sb  = smem_base + (c % GEMM_STAGES) * GEMM_STAGE_BYTES;
        const uint32_t aRow = (uint32_t)(warp_m * 32) + lrow;
        const uint32_t bRow = (uint32_t)(warp_n * 64) + lrow;

#pragma unroll
        for (int kk = 0; kk < 4; kk++) {
            uint32_t a[2][4];
#pragma unroll
            for (int mt = 0; mt < 2; mt++) {
                uint32_t off = (aRow + mt * 16) * 128 + kk * 32 + lcol;
                LDSM_X4(a[mt][0], a[mt][1], a[mt][2], a[mt][3], sb + SW128(off));
            }
            uint32_t b[4][4];
#pragma unroll
            for (int nt2 = 0; nt2 < 4; nt2++) {
                uint32_t off = (bRow + nt2 * 16) * 128 + kk * 32 + lcol;
                LDSM_X4(b[nt2][0], b[nt2][1], b[nt2][2], b[nt2][3],
                        sb + 16384u + SW128(off));
            }
#pragma unroll
            for (int mt = 0; mt < 2; mt++)
#pragma unroll
                for (int nt2 = 0; nt2 < 4; nt2++) {
                    MMA_16816(acc[mt][nt2 * 2 + 0], a[mt], b[nt2][0], b[nt2][2]);
                    MMA_16816(acc[mt][nt2 * 2 + 1], a[mt], b[nt2][1], b[nt2][3]);
                }
        }
    }

    const int er = lane >> 2;
    const int ec = (lane & 3) * 2;
#pragma unroll
    for (int mt = 0; mt < 2; mt++) {
        const int r0 = m0 + warp_m * 32 + mt * 16 + er;
#pragma unroll
        for (int nt = 0; nt < 8; nt++) {
            const int col = n0 + warp_n * 64 + nt * 8 + ec;
            const float bx = bias[col], by = bias[col + 1];
            float* p = C + (size_t)r0 * TE + col;
            *(float2*)p            = make_float2(acc[mt][nt][0] + bx, acc[mt][nt][1] + by);
            *(float2*)(p + 8 * TE) = make_float2(acc[mt][nt][2] + bx, acc[mt][nt][3] + by);
        }
    }
#undef ISSUE_STAGE
}

// ---------------------------------------------------------------------------
// Attention-column kernel v7: engineered for 2 CTAs/SM + one wave.
//  - 3-term split scores (hh+hm+mh)  -> half MMA work, 2 smem planes each
//  - Es stored fp16 [64][512] (64KB) -> logit error ~2e-6 (washed regime)
//  - K tiles 64 rows (8 kt), colacc in registers
//  smem = 64K(Es) + 16K(Q) + 16K(K) + 1.5K = 97.5KB -> 2 CTAs/SM; grid 256
//  fits one wave (296 slots). __launch_bounds__(256,2) caps regs at 128.
// ---------------------------------------------------------------------------
#define OFF_ES  0
#define OFF_QS  65536
#define OFF_KS  (OFF_QS + 2 * 8192)              // 81920
#define OFF_DEN (OFF_KS + 2 * 8192)              // 98304
#define OFF_INV (OFF_DEN + 128 * 8)              // 99328
#define ATTN_SMEM (OFF_INV + 64 * 8)             // 99840

__global__ __launch_bounds__(256, 2) void attn_col_kernel()
{
    extern __shared__ char sm[];
    const uint32_t sb = smem_u32(sm);
    __half* EsH    = (__half*)sm;                // [64][512]
    double* den2   = (double*)(sm + OFF_DEN);    // [64][2]
    double* invd   = (double*)(sm + OFF_INV);    // [64]

    const int t = threadIdx.x, lane = t & 31, wid = t >> 5;
    const int wm = wid & 3, wn = wid >> 2;       // wm: 16-row group; wn: 32-col half
    const int bh = blockIdx.x;

    const char* Qg = (const char*)(g_Qs2 + (size_t)bh * TS * 192);
    const char* Kg = (const char*)(g_Ks2 + (size_t)bh * TS * 192);

    double a0 = 0.0, a1 = 0.0;                   // colacc for s = t, t+256

    const uint32_t lrow = lane & 15;
    const uint32_t lcol = (lane >> 4) * 16;
    const int fr = lane >> 2;
    const int fc = (lane & 3) * 2;
    const int segA3[3] = {0, 0, 1};
    const int segB3[3] = {0, 1, 0};

    // loader lanes: row = t>>2 (0..63), 4 x 16B units u = (t&3)*4 + j
    const int ldrow = t >> 2;
    const int ldq   = t & 3;
    uint32_t ldOff[4];
#pragma unroll
    for (int j = 0; j < 4; j++) {
        int u = ldq * 4 + j;
        int seg = u >> 3, wi = (u & 7) * 16;
        ldOff[j] = seg * 8192 + SW128(ldrow * 128 + wi);
    }

    for (int qt = 0; qt < 8; qt++) {
        __syncthreads();   // prev colacc's Es/invd reads done
        // Q tile (hi+mid planes of 64 rows): first 256B of each 384B row
        {
            const char* src = Qg + (size_t)(qt * 64 + ldrow) * 384 + ldq * 64;
#pragma unroll
            for (int j = 0; j < 4; j++)
                CP_ASYNC16(sb + OFF_QS + ldOff[j], src + j * 16);
        }
        CP_COMMIT();
        if (t < 128) den2[t] = 0.0;

        for (int kt = 0; kt < 8; kt++) {
            __syncthreads();   // prev kt's LDSM reads of KS done; den2 reset seen
            {
                const char* src = Kg + (size_t)(kt * 64 + ldrow) * 384 + ldq * 64;
#pragma unroll
                for (int j = 0; j < 4; j++)
                    CP_ASYNC16(sb + OFF_KS + ldOff[j], src + j * 16);
            }
            CP_COMMIT();
            CP_WAIT0();        // K (and Q at kt==0)
            __syncthreads();

            float acc[4][4];
#pragma unroll
            for (int i = 0; i < 4; i++)
#pragma unroll
                for (int k = 0; k < 4; k++) acc[i][k] = 0.f;

#pragma unroll
            for (int ch = 0; ch < 3; ch++) {
                const uint32_t abase = sb + OFF_QS + segA3[ch] * 8192;
                const uint32_t bbase = sb + OFF_KS + segB3[ch] * 8192;
#pragma unroll
                for (int kk = 0; kk < 4; kk++) {
                    uint32_t a[4];
                    LDSM_X4(a[0], a[1], a[2], a[3],
                            abase + SW128((wm * 16 + lrow) * 128 + kk * 32 + lcol));
#pragma unroll
                    for (int nt2 = 0; nt2 < 2; nt2++) {
                        uint32_t b[4];
                        LDSM_X4(b[0], b[1], b[2], b[3],
                                bbase + SW128((wn * 32 + nt2 * 16 + lrow) * 128 + kk * 32 + lcol));
                        MMA_16816(acc[nt2 * 2 + 0], a, b[0], b[2]);
                        MMA_16816(acc[nt2 * 2 + 1], a, b[1], b[3]);
                    }
                }
            }

            // epilogue: exp, fp16 Es stores, fp64 row sums
            const int r0 = wm * 16 + fr;
            double d0 = 0.0, d1 = 0.0;
#pragma unroll
            for (int nt = 0; nt < 4; nt++) {
                const int col = kt * 64 + wn * 32 + nt * 8 + fc;
                float e0 = fast_expf(fmaf(acc[nt][0], 0.125f, 1.0f));
                float e1 = fast_expf(fmaf(acc[nt][1], 0.125f, 1.0f));
                float e2 = fast_expf(fmaf(acc[nt][2], 0.125f, 1.0f));
                float e3 = fast_expf(fmaf(acc[nt][3], 0.125f, 1.0f));
                *(__half2*)&EsH[r0 * 512 + col]       = __floats2half2_rn(e0, e1);
                *(__half2*)&EsH[(r0 + 8) * 512 + col] = __floats2half2_rn(e2, e3);
                d0 += (double)e0 + (double)e1;
                d1 += (double)e2 + (double)e3;
            }
            d0 += __shfl_xor_sync(0xffffffffu, d0, 1);
            d0 += __shfl_xor_sync(0xffffffffu, d0, 2);
            d1 += __shfl_xor_sync(0xffffffffu, d1, 1);
            d1 += __shfl_xor_sync(0xffffffffu, d1, 2);
            if ((lane & 3) == 0) {
                den2[r0 * 2 + wn]       += d0;
                den2[(r0 + 8) * 2 + wn] += d1;
            }
        }

        __syncthreads();   // all den2 writes + Es stores done
        if (t < 64) invd[t] = 1.0 / (den2[t * 2] + den2[t * 2 + 1]);
        __syncthreads();

#pragma unroll 8
        for (int rr = 0; rr < 64; rr++) {
            double iv = invd[rr];
            a0 = fma((double)__half2float(EsH[rr * 512 + t]),       iv, a0);
            a1 = fma((double)__half2float(EsH[rr * 512 + t + 256]), iv, a1);
        }
    }

    g_colpart[(size_t)bh * TS + t]       = a0;
    g_colpart[(size_t)bh * TS + t + 256] = a1;
}

// ---------------------------------------------------------------------------
// col -> log_softmax logits (fp64, deterministic tree reductions)
// ---------------------------------------------------------------------------
__global__ __launch_bounds__(512) void logits_kernel()
{
    __shared__ double red[512];
    const int b = blockIdx.x;
    const int s = threadIdx.x;

    double v = 0.0;
#pragma unroll
    for (int h = 0; h < TH; h++)
        v += g_colpart[((size_t)b * TH + h) * TS + s];

    red[s] = v;
    __syncthreads();
    for (int off = 256; off > 0; off >>= 1) {
        if (s < off) { double o = red[s + off]; if (o > red[s]) red[s] = o; }
        __syncthreads();
    }
    double m = red[0];
    __syncthreads();
    red[s] = exp(v - m);
    __syncthreads();
    for (int off = 256; off > 0; off >>= 1) {
        if (s < off) red[s] += red[s + off];
        __syncthreads();
    }
    double lse = m + log(red[0]);
    g_logits[(size_t)b * TS + s] = v - lse;
}

// ---------------------------------------------------------------------------
// Threefry-2x32 (JAX-exact, PARTITIONABLE): bits = o0 ^ o1, counter (0, i)
// ---------------------------------------------------------------------------
__device__ __forceinline__ void threefry2x32(
    unsigned k0, unsigned k1, unsigned x0, unsigned x1,
    unsigned& o0, unsigned& o1)
{
    const unsigned ks0 = k0, ks1 = k1, ks2 = k0 ^ k1 ^ 0x1BD11BDAu;
    x0 += ks0; x1 += ks1;
#define TF_RND(r) { x0 += x1; x1 = __funnelshift_l(x1, x1, r); x1 ^= x0; }
    TF_RND(13) TF_RND(15) TF_RND(26) TF_RND(6)   x0 += ks1; x1 += ks2 + 1u;
    TF_RND(17) TF_RND(29) TF_RND(16) TF_RND(24)  x0 += ks2; x1 += ks0 + 2u;
    TF_RND(13) TF_RND(15) TF_RND(26) TF_RND(6)   x0 += ks0; x1 += ks1 + 3u;
    TF_RND(17) TF_RND(29) TF_RND(16) TF_RND(24)  x0 += ks1; x1 += ks2 + 4u;
    TF_RND(13) TF_RND(15) TF_RND(26) TF_RND(6)   x0 += ks2; x1 += ks0 + 5u;
#undef TF_RND
    o0 = x0; o1 = x1;
}

// ---------------------------------------------------------------------------
// sample_kernel (validated R9): fp32 fast path + selective fp64 verification
// ---------------------------------------------------------------------------
__global__ __launch_bounds__(256) void sample_kernel(
    const float* __restrict__ tokens, float* __restrict__ out)
{
    const int warp = blockIdx.x * 8 + (threadIdx.x >> 5);   // 0..16383 = b*1024+j
    const int lane = threadIdx.x & 31;
    const int b = warp >> 10;
    const int j = warp & 1023;

    const double* lg = g_logits + (size_t)b * TS;

    float vreg[16];
    float best32 = -3.0e38f;
#pragma unroll
    for (int si = 0; si < 16; si++) {
        int s = lane + si * 32;
        unsigned i = (unsigned)warp * 512u + (unsigned)s;
        unsigned o0, o1;
        threefry2x32(0u, 42u, 0u, i, o0, o1);
        unsigned bits = o0 ^ o1;
        float f = __uint_as_float((bits >> 9) | 0x3f800000u) - 1.0f;
        float u = fmaxf(f, 1.17549435e-38f);
        float g32 = -logf(-logf(u));
        float v32 = g32 + (float)lg[s];
        vreg[si] = v32;
        best32 = fmaxf(best32, v32);
    }
#pragma unroll
    for (int off = 16; off > 0; off >>= 1)
        best32 = fmaxf(best32, __shfl_xor_sync(0xffffffffu, best32, off));

    const float thresh = best32 - 1.0e-4f;
    double best = -1.0e300;
    int    bi   = 0x7fffffff;
#pragma unroll
    for (int si = 0; si < 16; si++) {
        if (vreg[si] >= thresh) {
            int s = lane + si * 32;
            unsigned i = (unsigned)warp * 512u + (unsigned)s;
            unsigned o0, o1;
            threefry2x32(0u, 42u, 0u, i, o0, o1);
            unsigned bits = o0 ^ o1;
            float f = __uint_as_float((bits >> 9) | 0x3f800000u) - 1.0f;
            float u = fmaxf(f, 1.17549435e-38f);
            double g = -log(-log((double)u));
            double v = g + lg[s];
            if (v > best) { best = v; bi = s; }
        }
    }

#pragma unroll
    for (int off = 16; off > 0; off >>= 1) {
        double ov = __shfl_down_sync(0xffffffffu, best, off);
        int    oi = __shfl_down_sync(0xffffffffu, bi,   off);
        if (ov > best || (ov == best && oi < bi)) { best = ov; bi = oi; }
    }

    if (lane == 0)
        out[warp] = tokens[((size_t)b * TS + (size_t)bi) * TE + (size_t)j];
}

// ---------------------------------------------------------------------------
extern "C" void kernel_launch(void* const* d_in, const int* in_sizes, int n_in,
                              void* d_out, int out_size)
{
    (void)in_sizes; (void)n_in; (void)out_size;
    const float* tokens = (const float*)d_in[0];
    const float* Wq     = (const float*)d_in[1];
    const float* bq     = (const float*)d_in[2];
    const float* Wk     = (const float*)d_in[3];
    const float* bk     = (const float*)d_in[4];
    float* out = (float*)d_out;

    cudaFuncSetAttribute(gemm_hmma_kernel,
                         cudaFuncAttributeMaxDynamicSharedMemorySize, GEMM_SMEM);
    cudaFuncSetAttribute(attn_col_kernel,
                         cudaFuncAttributeMaxDynamicSharedMemorySize, ATTN_SMEM);

    split_inputs_kernel<<<10240, 256>>>(tokens, Wq, Wk);            // 0
    gemm_hmma_kernel<<<dim3(8, 64, 2), 256, GEMM_SMEM>>>(bq, bk);   // 1
    split_qk_kernel<<<dim3(8192, 1, 2), 256>>>();                   // 2
    attn_col_kernel<<<256, 256, ATTN_SMEM>>>();                     // 3 <- ncu capture
    logits_kernel<<<16, 512>>>();                                   // 4
    sample_kernel<<<2048, 256>>>(tokens, out);                      // 5
}

// round 16
// speedup vs baseline: 2.6708x; 1.2063x over previous
#include <cuda_runtime.h>
#include <cuda_bf16.h>
#include <cuda_fp16.h>
#include <math.h>
#include <stdint.h>

#define TB 16
#define TS 512
#define TE 1024
#define TH 16
#define TD 64
#define KSPLIT 3072          // 3 * TE (bf16 hi|mid|lo splits along K)

// Scratch (device globals: allocation-free rule)
static __device__ float  g_Q[(size_t)TB * TS * TE];
static __device__ float  g_K[(size_t)TB * TS * TE];
static __device__ double g_colpart[TB * TH * TS];
static __device__ double g_logits[TB * TS];
static __device__ __align__(128) __nv_bfloat16 g_As[(size_t)TB * TS * KSPLIT]; // tokens split
static __device__ __align__(128) __nv_bfloat16 g_Ws[(size_t)2 * TE * KSPLIT];  // Wq/Wk split
// per-head bf16 splits of Q/K: [bh][512 rows][3 segs x 64] (row = 192 bf16)
static __device__ __align__(128) __nv_bfloat16 g_Qs2[(size_t)TB * TH * TS * 192];
static __device__ __align__(128) __nv_bfloat16 g_Ks2[(size_t)TB * TH * TS * 192];

// ---------------------------------------------------------------------------
// PTX helpers (sm_80-class only: mma.sync / ldmatrix / cp.async — NO tcgen05)
// ---------------------------------------------------------------------------
__device__ __forceinline__ uint32_t smem_u32(const void* p) {
    uint32_t a;
    asm("{ .reg .u64 t; cvta.to.shared.u64 t, %1; cvt.u32.u64 %0, t; }" : "=r"(a) : "l"(p));
    return a;
}
#define SW128(o) ((o) ^ ((((uint32_t)(o)) >> 3) & 0x70u))

#define CP_ASYNC16(dst, src) \
    asm volatile("cp.async.cg.shared.global [%0], [%1], 16;" :: "r"(dst), "l"(src))
#define CP_COMMIT()  asm volatile("cp.async.commit_group;" ::: "memory")
#define CP_WAIT1()   asm volatile("cp.async.wait_group 1;" ::: "memory")
#define CP_WAIT0()   asm volatile("cp.async.wait_group 0;" ::: "memory")

#define LDSM_X4(r0, r1, r2, r3, a) \
    asm volatile("ldmatrix.sync.aligned.m8n8.x4.shared.b16 {%0,%1,%2,%3}, [%4];" \
                 : "=r"(r0), "=r"(r1), "=r"(r2), "=r"(r3) : "r"(a))

#define MMA_16816(D, A, B0, B1) \
    asm volatile("mma.sync.aligned.m16n8k16.row.col.f32.bf16.bf16.f32 " \
                 "{%0,%1,%2,%3}, {%4,%5,%6,%7}, {%8,%9}, {%0,%1,%2,%3};" \
                 : "+f"((D)[0]), "+f"((D)[1]), "+f"((D)[2]), "+f"((D)[3]) \
                 : "r"((A)[0]), "r"((A)[1]), "r"((A)[2]), "r"((A)[3]), \
                   "r"(B0), "r"(B1))

// ---------------------------------------------------------------------------
// Deterministic FMA-pipe exp
// ---------------------------------------------------------------------------
__device__ __forceinline__ float fast_expf(float x) {
    const float LOG2E   = 1.4426950408889634f;
    const float LN2_HI  = 0.693145751953125f;
    const float LN2_LO  = 1.428606765330187e-06f;
    float y  = x * LOG2E;
    float r  = rintf(y);
    int   ri = (int)r;
    float t  = fmaf(-r, LN2_HI, x);
    t = fmaf(-r, LN2_LO, t);
    float p = 1.9841269841e-4f;
    p = fmaf(p, t, 1.3888888889e-3f);
    p = fmaf(p, t, 8.3333333333e-3f);
    p = fmaf(p, t, 4.1666666667e-2f);
    p = fmaf(p, t, 1.6666666667e-1f);
    p = fmaf(p, t, 0.5f);
    p = fmaf(p, t, 1.0f);
    p = fmaf(p, t, 1.0f);
    return p * __int_as_float((ri + 127) << 23);
}

// ---------------------------------------------------------------------------
// Exact 3-way bf16 split
// ---------------------------------------------------------------------------
__device__ __forceinline__ void split3(float x, unsigned short& h, unsigned short& m,
                                       unsigned short& l) {
    __nv_bfloat16 bh = __float2bfloat16_rn(x);
    float r  = x - __bfloat162float(bh);
    __nv_bfloat16 bm = __float2bfloat16_rn(r);
    float r2 = r - __bfloat162float(bm);
    __nv_bfloat16 bl = __float2bfloat16_rn(r2);
    h = __bfloat16_as_ushort(bh);
    m = __bfloat16_as_ushort(bm);
    l = __bfloat16_as_ushort(bl);
}

__device__ __forceinline__ void split_store4s(const float4 v, __nv_bfloat16* dst, int stride) {
    unsigned short h[4], m[4], l[4];
    split3(v.x, h[0], m[0], l[0]);
    split3(v.y, h[1], m[1], l[1]);
    split3(v.z, h[2], m[2], l[2]);
    split3(v.w, h[3], m[3], l[3]);
    uint2 uh = make_uint2((uint32_t)h[0] | ((uint32_t)h[1] << 16),
                          (uint32_t)h[2] | ((uint32_t)h[3] << 16));
    uint2 um = make_uint2((uint32_t)m[0] | ((uint32_t)m[1] << 16),
                          (uint32_t)m[2] | ((uint32_t)m[3] << 16));
    uint2 ul = make_uint2((uint32_t)l[0] | ((uint32_t)l[1] << 16),
                          (uint32_t)l[2] | ((uint32_t)l[3] << 16));
    *(uint2*)(dst)              = uh;
    *(uint2*)(dst + stride)     = um;
    *(uint2*)(dst + 2 * stride) = ul;
}

// fused input split: blocks [0,8192) tokens -> g_As; [8192,9216) Wq; [9216,10240) Wk
__global__ __launch_bounds__(256) void split_inputs_kernel(
    const float* __restrict__ tokens,
    const float* __restrict__ Wq, const float* __restrict__ Wk)
{
    int blk = blockIdx.x;
    if (blk < 8192) {
        size_t i = (size_t)blk * 256 + threadIdx.x;
        float4 v = ((const float4*)tokens)[i];
        size_t row = i >> 8;
        int    c4  = (int)(i & 255) * 4;
        split_store4s(v, g_As + row * KSPLIT + c4, TE);
    } else {
        int sel = (blk >= 9216) ? 1 : 0;
        size_t i = (size_t)(blk - 8192 - sel * 1024) * 256 + threadIdx.x;
        const float* W = sel ? Wk : Wq;
        float4 v = ((const float4*)W)[i];
        size_t row = i >> 8;
        int    c4  = (int)(i & 255) * 4;
        split_store4s(v, g_Ws + (size_t)sel * TE * KSPLIT + row * KSPLIT + c4, TE);
    }
}

// g_Q/g_K fp32 [8192,1024] -> per-head split [bh][512][3*64] bf16
__global__ __launch_bounds__(256) void split_qk_kernel()
{
    const float*    src = blockIdx.z ? g_K : g_Q;
    __nv_bfloat16*  dst = blockIdx.z ? g_Ks2 : g_Qs2;
    size_t i = (size_t)blockIdx.x * 256 + threadIdx.x;
    float4 v = ((const float4*)src)[i];
    size_t r = i >> 8;
    int    c4 = (int)(i & 255) * 4;
    int h = c4 >> 6, d = c4 & 63;
    int b = (int)(r >> 9), s = (int)(r & 511);
    __nv_bfloat16* o = dst + (((size_t)(b * TH + h) * TS + s) * 192 + d);
    split_store4s(v, o, 64);
}

// ---------------------------------------------------------------------------
// HMMA GEMM: 3-term bf16-split product (hh + hm + mh) — validated R14.
// ---------------------------------------------------------------------------
#define GEMM_STAGES 3
#define GEMM_STAGE_BYTES 32768
#define GEMM_SMEM (GEMM_STAGES * GEMM_STAGE_BYTES)
#define NCHUNK 48

__global__ __launch_bounds__(256) void gemm_hmma_kernel(const float* __restrict__ bq,
                                                        const float* __restrict__ bk)
{
    extern __shared__ char dsm[];
    const uint32_t smem_base = smem_u32(dsm);

    const int t    = threadIdx.x;
    const int lane = t & 31, wid = t >> 5;
    const int warp_m = wid & 3;
    const int warp_n = wid >> 2;
    const int sel = blockIdx.z;
    const int m0  = blockIdx.y * 128;
    const int n0  = blockIdx.x * 128;

    float*       C    = sel ? g_K : g_Q;
    const float* bias = sel ? bk : bq;

    const int row  = t >> 1;
    const int half = t & 1;
    const char* aG = (const char*)(g_As + (size_t)(m0 + row) * KSPLIT + half * 32);
    const char* bG = (const char*)(g_Ws + (size_t)sel * TE * KSPLIT
                                        + (size_t)(n0 + row) * KSPLIT + half * 32);
    uint32_t dOffA[4], dOffB[4];
#pragma unroll
    for (int i = 0; i < 4; i++) {
        uint32_t o = SW128((uint32_t)(row * 128 + half * 64 + i * 16));
        dOffA[i] = o;
        dOffB[i] = 16384u + o;
    }
    const uint32_t segA = 0x100u;   // [0,0,1]
    const uint32_t segB = 0x010u;   // [0,1,0]

#define ISSUE_STAGE(c_) do {                                                   \
    int _c = (c_);                                                             \
    int _seg = _c >> 4, _kc = _c & 15;                                         \
    int _pa = (segA >> (_seg * 4)) & 7, _pb = (segB >> (_seg * 4)) & 7;        \
    uint32_t _sb = smem_base + (_c % GEMM_STAGES) * GEMM_STAGE_BYTES;          \
    const char* _as = aG + (_pa * 1024 + _kc * 64) * 2;                        \
    const char* _bs = bG + (_pb * 1024 + _kc * 64) * 2;                        \
    _Pragma("unroll")                                                          \
    for (int _i = 0; _i < 4; _i++) {                                           \
        CP_ASYNC16(_sb + dOffA[_i], _as + _i * 16);                            \
        CP_ASYNC16(_sb + dOffB[_i], _bs + _i * 16);                            \
    }                                                                          \
    CP_COMMIT();                                                               \
} while (0)

    float acc[2][8][4];
#pragma unroll
    for (int i = 0; i < 2; i++)
#pragma unroll
        for (int j = 0; j < 8; j++)
#pragma unroll
            for (int k = 0; k < 4; k++) acc[i][j][k] = 0.f;

    const uint32_t lrow = lane & 15;
    const uint32_t lcol = (lane >> 4) * 16;

    ISSUE_STAGE(0);
    ISSUE_STAGE(1);

    for (int c = 0; c < NCHUNK; c++) {
        if (c < NCHUNK - 1) CP_WAIT1(); else CP_WAIT0();
        __syncthreads();
        if (c + 2 < NCHUNK) ISSUE_STAGE(c + 2);

        const uint32_t sb  = smem_base + (c % GEMM_STAGES) * GEMM_STAGE_BYTES;
        const uint32_t aRow = (uint32_t)(warp_m * 32) + lrow;
        const uint32_t bRow = (uint32_t)(warp_n * 64) + lrow;

#pragma unroll
        for (int kk = 0; kk < 4; kk++) {
            uint32_t a[2][4];
#pragma unroll
            for (int mt = 0; mt < 2; mt++) {
                uint32_t off = (aRow + mt * 16) * 128 + kk * 32 + lcol;
                LDSM_X4(a[mt][0], a[mt][1], a[mt][2], a[mt][3], sb + SW128(off));
            }
            uint32_t b[4][4];
#pragma unroll
            for (int nt2 = 0; nt2 < 4; nt2++) {
                uint32_t off = (bRow + nt2 * 16) * 128 + kk * 32 + lcol;
                LDSM_X4(b[nt2][0], b[nt2][1], b[nt2][2], b[nt2][3],
                        sb + 16384u + SW128(off));
            }
#pragma unroll
            for (int mt = 0; mt < 2; mt++)
#pragma unroll
                for (int nt2 = 0; nt2 < 4; nt2++) {
                    MMA_16816(acc[mt][nt2 * 2 + 0], a[mt], b[nt2][0], b[nt2][2]);
                    MMA_16816(acc[mt][nt2 * 2 + 1], a[mt], b[nt2][1], b[nt2][3]);
                }
        }
    }

    const int er = lane >> 2;
    const int ec = (lane & 3) * 2;
#pragma unroll
    for (int mt = 0; mt < 2; mt++) {
        const int r0 = m0 + warp_m * 32 + mt * 16 + er;
#pragma unroll
        for (int nt = 0; nt < 8; nt++) {
            const int col = n0 + warp_n * 64 + nt * 8 + ec;
            const float bx = bias[col], by = bias[col + 1];
            float* p = C + (size_t)r0 * TE + col;
            *(float2*)p            = make_float2(acc[mt][nt][0] + bx, acc[mt][nt][1] + by);
            *(float2*)(p + 8 * TE) = make_float2(acc[mt][nt][2] + bx, acc[mt][nt][3] + by);
        }
    }
#undef ISSUE_STAGE
}

// ---------------------------------------------------------------------------
// Attention-column kernel v8: v7 + double-buffered K pipeline + fp32 row sums.
//  v7's per-kt CP_WAIT0 exposed a full L2 round trip 64x per block, and the
//  epilogue carried 8-deep serial fp64 DADD chains. Now K(kt+1) is always in
//  flight during kt's compute (gemm-style wait<=1), and per-kt row sums
//  accumulate in fp32 (one fp64 add per warp-quad per kt into den2).
//  smem = 64K(Es fp16) + 16K(Q) + 32K(K x2) + 1.5K = 113.5KB -> 2 CTAs/SM.
// ---------------------------------------------------------------------------
#define OFF_ES  0
#define OFF_QS  65536
#define OFF_KS  (OFF_QS + 2 * 8192)              // 81920; two 16KB buffers
#define OFF_DEN (OFF_KS + 2 * 16384)             // 114688
#define OFF_INV (OFF_DEN + 128 * 8)              // 115712
#define ATTN_SMEM (OFF_INV + 64 * 8)             // 116224

__global__ __launch_bounds__(256, 2) void attn_col_kernel()
{
    extern __shared__ char sm[];
    const uint32_t sb = smem_u32(sm);
    __half* EsH    = (__half*)sm;                // [64][512]
    double* den2   = (double*)(sm + OFF_DEN);    // [64][2]
    double* invd   = (double*)(sm + OFF_INV);    // [64]

    const int t = threadIdx.x, lane = t & 31, wid = t >> 5;
    const int wm = wid & 3, wn = wid >> 2;       // wm: 16-row group; wn: 32-col half
    const int bh = blockIdx.x;

    const char* Qg = (const char*)(g_Qs2 + (size_t)bh * TS * 192);
    const char* Kg = (const char*)(g_Ks2 + (size_t)bh * TS * 192);

    double a0 = 0.0, a1 = 0.0;                   // colacc for s = t, t+256

    const uint32_t lrow = lane & 15;
    const uint32_t lcol = (lane >> 4) * 16;
    const int fr = lane >> 2;
    const int fc = (lane & 3) * 2;
    const int segA3[3] = {0, 0, 1};
    const int segB3[3] = {0, 1, 0};

    // loader lanes: row = t>>2 (0..63), 4 x 16B units u = (t&3)*4 + j
    const int ldrow = t >> 2;
    const int ldq   = t & 3;
    uint32_t ldOff[4];
#pragma unroll
    for (int j = 0; j < 4; j++) {
        int u = ldq * 4 + j;
        int seg = u >> 3, wi = (u & 7) * 16;
        ldOff[j] = seg * 8192 + SW128(ldrow * 128 + wi);
    }

#define ISSUE_K(kt_) do {                                                      \
    int _kt = (kt_);                                                           \
    uint32_t _kb = sb + OFF_KS + (_kt & 1) * 16384;                            \
    const char* _src = Kg + (size_t)(_kt * 64 + ldrow) * 384 + ldq * 64;       \
    _Pragma("unroll")                                                          \
    for (int _j = 0; _j < 4; _j++)                                             \
        CP_ASYNC16(_kb + ldOff[_j], _src + _j * 16);                           \
    CP_COMMIT();                                                               \
} while (0)

    for (int qt = 0; qt < 8; qt++) {
        __syncthreads();   // prev colacc's Es/invd reads done
        // Q tile (hi+mid planes of 64 rows)
        {
            const char* src = Qg + (size_t)(qt * 64 + ldrow) * 384 + ldq * 64;
#pragma unroll
            for (int j = 0; j < 4; j++)
                CP_ASYNC16(sb + OFF_QS + ldOff[j], src + j * 16);
        }
        CP_COMMIT();
        if (t < 128) den2[t] = 0.0;
        ISSUE_K(0);
        ISSUE_K(1);

        for (int kt = 0; kt < 8; kt++) {
            if (kt < 7) CP_WAIT1(); else CP_WAIT0();   // Q..K(kt) arrived
            __syncthreads();

            const uint32_t kb = sb + OFF_KS + (kt & 1) * 16384;
            float acc[4][4];
#pragma unroll
            for (int i = 0; i < 4; i++)
#pragma unroll
                for (int k = 0; k < 4; k++) acc[i][k] = 0.f;

#pragma unroll
            for (int ch = 0; ch < 3; ch++) {
                const uint32_t abase = sb + OFF_QS + segA3[ch] * 8192;
                const uint32_t bbase = kb + segB3[ch] * 8192;
#pragma unroll
                for (int kk = 0; kk < 4; kk++) {
                    uint32_t a[4];
                    LDSM_X4(a[0], a[1], a[2], a[3],
                            abase + SW128((wm * 16 + lrow) * 128 + kk * 32 + lcol));
#pragma unroll
                    for (int nt2 = 0; nt2 < 2; nt2++) {
                        uint32_t b[4];
                        LDSM_X4(b[0], b[1], b[2], b[3],
                                bbase + SW128((wn * 32 + nt2 * 16 + lrow) * 128 + kk * 32 + lcol));
                        MMA_16816(acc[nt2 * 2 + 0], a, b[0], b[2]);
                        MMA_16816(acc[nt2 * 2 + 1], a, b[1], b[3]);
                    }
                }
            }

            // epilogue: exp, fp16 Es stores, fp32 row sums (one fp64 add/quad)
            const int r0 = wm * 16 + fr;
            float d0f = 0.f, d1f = 0.f;
#pragma unroll
            for (int nt = 0; nt < 4; nt++) {
                const int col = kt * 64 + wn * 32 + nt * 8 + fc;
                float e0 = fast_expf(fmaf(acc[nt][0], 0.125f, 1.0f));
                float e1 = fast_expf(fmaf(acc[nt][1], 0.125f, 1.0f));
                float e2 = fast_expf(fmaf(acc[nt][2], 0.125f, 1.0f));
                float e3 = fast_expf(fmaf(acc[nt][3], 0.125f, 1.0f));
                *(__half2*)&EsH[r0 * 512 + col]       = __floats2half2_rn(e0, e1);
                *(__half2*)&EsH[(r0 + 8) * 512 + col] = __floats2half2_rn(e2, e3);
                d0f += e0 + e1;
                d1f += e2 + e3;
            }
            d0f += __shfl_xor_sync(0xffffffffu, d0f, 1);
            d0f += __shfl_xor_sync(0xffffffffu, d0f, 2);
            d1f += __shfl_xor_sync(0xffffffffu, d1f, 1);
            d1f += __shfl_xor_sync(0xffffffffu, d1f, 2);
            if ((lane & 3) == 0) {
                den2[r0 * 2 + wn]       += (double)d0f;
                den2[(r0 + 8) * 2 + wn] += (double)d1f;
            }
            __syncthreads();   // LDSM reads + den2 adds done
            if (kt + 2 < 8) ISSUE_K(kt + 2);
        }

        if (t < 64) invd[t] = 1.0 / (den2[t * 2] + den2[t * 2 + 1]);
        __syncthreads();

#pragma unroll 8
        for (int rr = 0; rr < 64; rr++) {
            double iv = invd[rr];
            a0 = fma((double)__half2float(EsH[rr * 512 + t]),       iv, a0);
            a1 = fma((double)__half2float(EsH[rr * 512 + t + 256]), iv, a1);
        }
    }
#undef ISSUE_K

    g_colpart[(size_t)bh * TS + t]       = a0;
    g_colpart[(size_t)bh * TS + t + 256] = a1;
}

// ---------------------------------------------------------------------------
// col -> log_softmax logits (fp64, deterministic tree reductions)
// ---------------------------------------------------------------------------
__global__ __launch_bounds__(512) void logits_kernel()
{
    __shared__ double red[512];
    const int b = blockIdx.x;
    const int s = threadIdx.x;

    double v = 0.0;
#pragma unroll
    for (int h = 0; h < TH; h++)
        v += g_colpart[((size_t)b * TH + h) * TS + s];

    red[s] = v;
    __syncthreads();
    for (int off = 256; off > 0; off >>= 1) {
        if (s < off) { double o = red[s + off]; if (o > red[s]) red[s] = o; }
        __syncthreads();
    }
    double m = red[0];
    __syncthreads();
    red[s] = exp(v - m);
    __syncthreads();
    for (int off = 256; off > 0; off >>= 1) {
        if (s < off) red[s] += red[s + off];
        __syncthreads();
    }
    double lse = m + log(red[0]);
    g_logits[(size_t)b * TS + s] = v - lse;
}

// ---------------------------------------------------------------------------
// Threefry-2x32 (JAX-exact, PARTITIONABLE): bits = o0 ^ o1, counter (0, i)
// ---------------------------------------------------------------------------
__device__ __forceinline__ void threefry2x32(
    unsigned k0, unsigned k1, unsigned x0, unsigned x1,
    unsigned& o0, unsigned& o1)
{
    const unsigned ks0 = k0, ks1 = k1, ks2 = k0 ^ k1 ^ 0x1BD11BDAu;
    x0 += ks0; x1 += ks1;
#define TF_RND(r) { x0 += x1; x1 = __funnelshift_l(x1, x1, r); x1 ^= x0; }
    TF_RND(13) TF_RND(15) TF_RND(26) TF_RND(6)   x0 += ks1; x1 += ks2 + 1u;
    TF_RND(17) TF_RND(29) TF_RND(16) TF_RND(24)  x0 += ks2; x1 += ks0 + 2u;
    TF_RND(13) TF_RND(15) TF_RND(26) TF_RND(6)   x0 += ks0; x1 += ks1 + 3u;
    TF_RND(17) TF_RND(29) TF_RND(16) TF_RND(24)  x0 += ks1; x1 += ks2 + 4u;
    TF_RND(13) TF_RND(15) TF_RND(26) TF_RND(6)   x0 += ks2; x1 += ks0 + 5u;
#undef TF_RND
    o0 = x0; o1 = x1;
}

// ---------------------------------------------------------------------------
// sample_kernel (validated R9): fp32 fast path + selective fp64 verification
// ---------------------------------------------------------------------------
__global__ __launch_bounds__(256) void sample_kernel(
    const float* __restrict__ tokens, float* __restrict__ out)
{
    const int warp = blockIdx.x * 8 + (threadIdx.x >> 5);   // 0..16383 = b*1024+j
    const int lane = threadIdx.x & 31;
    const int b = warp >> 10;
    const int j = warp & 1023;

    const double* lg = g_logits + (size_t)b * TS;

    float vreg[16];
    float best32 = -3.0e38f;
#pragma unroll
    for (int si = 0; si < 16; si++) {
        int s = lane + si * 32;
        unsigned i = (unsigned)warp * 512u + (unsigned)s;
        unsigned o0, o1;
        threefry2x32(0u, 42u, 0u, i, o0, o1);
        unsigned bits = o0 ^ o1;
        float f = __uint_as_float((bits >> 9) | 0x3f800000u) - 1.0f;
        float u = fmaxf(f, 1.17549435e-38f);
        float g32 = -logf(-logf(u));
        float v32 = g32 + (float)lg[s];
        vreg[si] = v32;
        best32 = fmaxf(best32, v32);
    }
#pragma unroll
    for (int off = 16; off > 0; off >>= 1)
        best32 = fmaxf(best32, __shfl_xor_sync(0xffffffffu, best32, off));

    const float thresh = best32 - 1.0e-4f;
    double best = -1.0e300;
    int    bi   = 0x7fffffff;
#pragma unroll
    for (int si = 0; si < 16; si++) {
        if (vreg[si] >= thresh) {
            int s = lane + si * 32;
            unsigned i = (unsigned)warp * 512u + (unsigned)s;
            unsigned o0, o1;
            threefry2x32(0u, 42u, 0u, i, o0, o1);
            unsigned bits = o0 ^ o1;
            float f = __uint_as_float((bits >> 9) | 0x3f800000u) - 1.0f;
            float u = fmaxf(f, 1.17549435e-38f);
            double g = -log(-log((double)u));
            double v = g + lg[s];
            if (v > best) { best = v; bi = s; }
        }
    }

#pragma unroll
    for (int off = 16; off > 0; off >>= 1) {
        double ov = __shfl_down_sync(0xffffffffu, best, off);
        int    oi = __shfl_down_sync(0xffffffffu, bi,   off);
        if (ov > best || (ov == best && oi < bi)) { best = ov; bi = oi; }
    }

    if (lane == 0)
        out[warp] = tokens[((size_t)b * TS + (size_t)bi) * TE + (size_t)j];
}

// ---------------------------------------------------------------------------
extern "C" void kernel_launch(void* const* d_in, const int* in_sizes, int n_in,
                              void* d_out, int out_size)
{
    (void)in_sizes; (void)n_in; (void)out_size;
    const float* tokens = (const float*)d_in[0];
    const float* Wq     = (const float*)d_in[1];
    const float* bq     = (const float*)d_in[2];
    const float* Wk     = (const float*)d_in[3];
    const float* bk     = (const float*)d_in[4];
    float* out = (float*)d_out;

    cudaFuncSetAttribute(gemm_hmma_kernel,
                         cudaFuncAttributeMaxDynamicSharedMemorySize, GEMM_SMEM);
    cudaFuncSetAttribute(attn_col_kernel,
                         cudaFuncAttributeMaxDynamicSharedMemorySize, ATTN_SMEM);

    split_inputs_kernel<<<10240, 256>>>(tokens, Wq, Wk);            // 0
    gemm_hmma_kernel<<<dim3(8, 64, 2), 256, GEMM_SMEM>>>(bq, bk);   // 1
    split_qk_kernel<<<dim3(8192, 1, 2), 256>>>();                   // 2
    attn_col_kernel<<<256, 256, ATTN_SMEM>>>();                     // 3 <- ncu capture
    logits_kernel<<<16, 512>>>();                                   // 4
    sample_kernel<<<2048, 256>>>(tokens, out);                      // 5
}

// round 17
// speedup vs baseline: 2.8250x; 1.0577x over previous
#include <cuda_runtime.h>
#include <cuda_bf16.h>
#include <cuda_fp16.h>
#include <math.h>
#include <stdint.h>

#define TB 16
#define TS 512
#define TE 1024
#define TH 16
#define TD 64
#define KSPLIT 3072          // 3 * TE (bf16 hi|mid|lo splits along K)

// Scratch (device globals: allocation-free rule)
static __device__ float  g_Q[(size_t)TB * TS * TE];
static __device__ float  g_K[(size_t)TB * TS * TE];
static __device__ double g_colpart[TB * TH * TS];
static __device__ double g_logits[TB * TS];
static __device__ __align__(128) __nv_bfloat16 g_As[(size_t)TB * TS * KSPLIT]; // tokens split
static __device__ __align__(128) __nv_bfloat16 g_Ws[(size_t)2 * TE * KSPLIT];  // Wq/Wk split
// per-head bf16 splits of Q/K: [bh][512 rows][3 segs x 64] (row = 192 bf16)
static __device__ __align__(128) __nv_bfloat16 g_Qs2[(size_t)TB * TH * TS * 192];
static __device__ __align__(128) __nv_bfloat16 g_Ks2[(size_t)TB * TH * TS * 192];

// ---------------------------------------------------------------------------
// PTX helpers (sm_80-class only: mma.sync / ldmatrix / cp.async — NO tcgen05)
// ---------------------------------------------------------------------------
__device__ __forceinline__ uint32_t smem_u32(const void* p) {
    uint32_t a;
    asm("{ .reg .u64 t; cvta.to.shared.u64 t, %1; cvt.u32.u64 %0, t; }" : "=r"(a) : "l"(p));
    return a;
}
#define SW128(o) ((o) ^ ((((uint32_t)(o)) >> 3) & 0x70u))

#define CP_ASYNC16(dst, src) \
    asm volatile("cp.async.cg.shared.global [%0], [%1], 16;" :: "r"(dst), "l"(src))
#define CP_COMMIT()  asm volatile("cp.async.commit_group;" ::: "memory")
#define CP_WAIT1()   asm volatile("cp.async.wait_group 1;" ::: "memory")
#define CP_WAIT0()   asm volatile("cp.async.wait_group 0;" ::: "memory")

#define LDSM_X4(r0, r1, r2, r3, a) \
    asm volatile("ldmatrix.sync.aligned.m8n8.x4.shared.b16 {%0,%1,%2,%3}, [%4];" \
                 : "=r"(r0), "=r"(r1), "=r"(r2), "=r"(r3) : "r"(a))

#define MMA_16816(D, A, B0, B1) \
    asm volatile("mma.sync.aligned.m16n8k16.row.col.f32.bf16.bf16.f32 " \
                 "{%0,%1,%2,%3}, {%4,%5,%6,%7}, {%8,%9}, {%0,%1,%2,%3};" \
                 : "+f"((D)[0]), "+f"((D)[1]), "+f"((D)[2]), "+f"((D)[3]) \
                 : "r"((A)[0]), "r"((A)[1]), "r"((A)[2]), "r"((A)[3]), \
                   "r"(B0), "r"(B1))

// ---------------------------------------------------------------------------
// Deterministic FMA-pipe exp
// ---------------------------------------------------------------------------
__device__ __forceinline__ float fast_expf(float x) {
    const float LOG2E   = 1.4426950408889634f;
    const float LN2_HI  = 0.693145751953125f;
    const float LN2_LO  = 1.428606765330187e-06f;
    float y  = x * LOG2E;
    float r  = rintf(y);
    int   ri = (int)r;
    float t  = fmaf(-r, LN2_HI, x);
    t = fmaf(-r, LN2_LO, t);
    float p = 1.9841269841e-4f;
    p = fmaf(p, t, 1.3888888889e-3f);
    p = fmaf(p, t, 8.3333333333e-3f);
    p = fmaf(p, t, 4.1666666667e-2f);
    p = fmaf(p, t, 1.6666666667e-1f);
    p = fmaf(p, t, 0.5f);
    p = fmaf(p, t, 1.0f);
    p = fmaf(p, t, 1.0f);
    return p * __int_as_float((ri + 127) << 23);
}

// ---------------------------------------------------------------------------
// Exact 3-way bf16 split
// ---------------------------------------------------------------------------
__device__ __forceinline__ void split3(float x, unsigned short& h, unsigned short& m,
                                       unsigned short& l) {
    __nv_bfloat16 bh = __float2bfloat16_rn(x);
    float r  = x - __bfloat162float(bh);
    __nv_bfloat16 bm = __float2bfloat16_rn(r);
    float r2 = r - __bfloat162float(bm);
    __nv_bfloat16 bl = __float2bfloat16_rn(r2);
    h = __bfloat16_as_ushort(bh);
    m = __bfloat16_as_ushort(bm);
    l = __bfloat16_as_ushort(bl);
}

__device__ __forceinline__ void split_store4s(const float4 v, __nv_bfloat16* dst, int stride) {
    unsigned short h[4], m[4], l[4];
    split3(v.x, h[0], m[0], l[0]);
    split3(v.y, h[1], m[1], l[1]);
    split3(v.z, h[2], m[2], l[2]);
    split3(v.w, h[3], m[3], l[3]);
    uint2 uh = make_uint2((uint32_t)h[0] | ((uint32_t)h[1] << 16),
                          (uint32_t)h[2] | ((uint32_t)h[3] << 16));
    uint2 um = make_uint2((uint32_t)m[0] | ((uint32_t)m[1] << 16),
                          (uint32_t)m[2] | ((uint32_t)m[3] << 16));
    uint2 ul = make_uint2((uint32_t)l[0] | ((uint32_t)l[1] << 16),
                          (uint32_t)l[2] | ((uint32_t)l[3] << 16));
    *(uint2*)(dst)              = uh;
    *(uint2*)(dst + stride)     = um;
    *(uint2*)(dst + 2 * stride) = ul;
}

// fused input split: blocks [0,8192) tokens -> g_As; [8192,9216) Wq; [9216,10240) Wk
__global__ __launch_bounds__(256) void split_inputs_kernel(
    const float* __restrict__ tokens,
    const float* __restrict__ Wq, const float* __restrict__ Wk)
{
    int blk = blockIdx.x;
    if (blk < 8192) {
        size_t i = (size_t)blk * 256 + threadIdx.x;
        float4 v = ((const float4*)tokens)[i];
        size_t row = i >> 8;
        int    c4  = (int)(i & 255) * 4;
        split_store4s(v, g_As + row * KSPLIT + c4, TE);
    } else {
        int sel = (blk >= 9216) ? 1 : 0;
        size_t i = (size_t)(blk - 8192 - sel * 1024) * 256 + threadIdx.x;
        const float* W = sel ? Wk : Wq;
        float4 v = ((const float4*)W)[i];
        size_t row = i >> 8;
        int    c4  = (int)(i & 255) * 4;
        split_store4s(v, g_Ws + (size_t)sel * TE * KSPLIT + row * KSPLIT + c4, TE);
    }
}

// g_Q/g_K fp32 [8192,1024] -> per-head split [bh][512][3*64] bf16
__global__ __launch_bounds__(256) void split_qk_kernel()
{
    const float*    src = blockIdx.z ? g_K : g_Q;
    __nv_bfloat16*  dst = blockIdx.z ? g_Ks2 : g_Qs2;
    size_t i = (size_t)blockIdx.x * 256 + threadIdx.x;
    float4 v = ((const float4*)src)[i];
    size_t r = i >> 8;
    int    c4 = (int)(i & 255) * 4;
    int h = c4 >> 6, d = c4 & 63;
    int b = (int)(r >> 9), s = (int)(r & 511);
    __nv_bfloat16* o = dst + (((size_t)(b * TH + h) * TS + s) * 192 + d);
    split_store4s(v, o, 64);
}

// ---------------------------------------------------------------------------
// HMMA GEMM: 3-term bf16-split product (hh + hm + mh) — validated R14.
// ---------------------------------------------------------------------------
#define GEMM_STAGES 3
#define GEMM_STAGE_BYTES 32768
#define GEMM_SMEM (GEMM_STAGES * GEMM_STAGE_BYTES)
#define NCHUNK 48

__global__ __launch_bounds__(256) void gemm_hmma_kernel(const float* __restrict__ bq,
                                                        const float* __restrict__ bk)
{
    extern __shared__ char dsm[];
    const uint32_t smem_base = smem_u32(dsm);

    const int t    = threadIdx.x;
    const int lane = t & 31, wid = t >> 5;
    const int warp_m = wid & 3;
    const int warp_n = wid >> 2;
    const int sel = blockIdx.z;
    const int m0  = blockIdx.y * 128;
    const int n0  = blockIdx.x * 128;

    float*       C    = sel ? g_K : g_Q;
    const float* bias = sel ? bk : bq;

    const int row  = t >> 1;
    const int half = t & 1;
    const char* aG = (const char*)(g_As + (size_t)(m0 + row) * KSPLIT + half * 32);
    const char* bG = (const char*)(g_Ws + (size_t)sel * TE * KSPLIT
                                        + (size_t)(n0 + row) * KSPLIT + half * 32);
    uint32_t dOffA[4], dOffB[4];
#pragma unroll
    for (int i = 0; i < 4; i++) {
        uint32_t o = SW128((uint32_t)(row * 128 + half * 64 + i * 16));
        dOffA[i] = o;
        dOffB[i] = 16384u + o;
    }
    const uint32_t segA = 0x100u;   // [0,0,1]
    const uint32_t segB = 0x010u;   // [0,1,0]

#define ISSUE_STAGE(c_) do {                                                   \
    int _c = (c_);                                                             \
    int _seg = _c >> 4, _kc = _c & 15;                                         \
    int _pa = (segA >> (_seg * 4)) & 7, _pb = (segB >> (_seg * 4)) & 7;        \
    uint32_t _sb = smem_base + (_c % GEMM_STAGES) * GEMM_STAGE_BYTES;          \
    const char* _as = aG + (_pa * 1024 + _kc * 64) * 2;                        \
    const char* _bs = bG + (_pb * 1024 + _kc * 64) * 2;                        \
    _Pragma("unroll")                                                          \
    for (int _i = 0; _i < 4; _i++) {                                           \
        CP_ASYNC16(_sb + dOffA[_i], _as + _i * 16);                            \
        CP_ASYNC16(_sb + dOffB[_i], _bs + _i * 16);                            \
    }                                                                          \
    CP_COMMIT();                                                               \
} while (0)

    float acc[2][8][4];
#pragma unroll
    for (int i = 0; i < 2; i++)
#pragma unroll
        for (int j = 0; j < 8; j++)
#pragma unroll
            for (int k = 0; k < 4; k++) acc[i][j][k] = 0.f;

    const uint32_t lrow = lane & 15;
    const uint32_t lcol = (lane >> 4) * 16;

    ISSUE_STAGE(0);
    ISSUE_STAGE(1);

    for (int c = 0; c < NCHUNK; c++) {
        if (c < NCHUNK - 1) CP_WAIT1(); else CP_WAIT0();
        __syncthreads();
        if (c + 2 < NCHUNK) ISSUE_STAGE(c + 2);

        const uint32_t sb  = smem_base + (c % GEMM_STAGES) * GEMM_STAGE_BYTES;
        const uint32_t aRow = (uint32_t)(warp_m * 32) + lrow;
        const uint32_t bRow = (uint32_t)(warp_n * 64) + lrow;

#pragma unroll
        for (int kk = 0; kk < 4; kk++) {
            uint32_t a[2][4];
#pragma unroll
            for (int mt = 0; mt < 2; mt++) {
                uint32_t off = (aRow + mt * 16) * 128 + kk * 32 + lcol;
                LDSM_X4(a[mt][0], a[mt][1], a[mt][2], a[mt][3], sb + SW128(off));
            }
            uint32_t b[4][4];
#pragma unroll
            for (int nt2 = 0; nt2 < 4; nt2++) {
                uint32_t off = (bRow + nt2 * 16) * 128 + kk * 32 + lcol;
                LDSM_X4(b[nt2][0], b[nt2][1], b[nt2][2], b[nt2][3],
                        sb + 16384u + SW128(off));
            }
#pragma unroll
            for (int mt = 0; mt < 2; mt++)
#pragma unroll
                for (int nt2 = 0; nt2 < 4; nt2++) {
                    MMA_16816(acc[mt][nt2 * 2 + 0], a[mt], b[nt2][0], b[nt2][2]);
                    MMA_16816(acc[mt][nt2 * 2 + 1], a[mt], b[nt2][1], b[nt2][3]);
                }
        }
    }

    const int er = lane >> 2;
    const int ec = (lane & 3) * 2;
#pragma unroll
    for (int mt = 0; mt < 2; mt++) {
        const int r0 = m0 + warp_m * 32 + mt * 16 + er;
#pragma unroll
        for (int nt = 0; nt < 8; nt++) {
            const int col = n0 + warp_n * 64 + nt * 8 + ec;
            const float bx = bias[col], by = bias[col + 1];
            float* p = C + (size_t)r0 * TE + col;
            *(float2*)p            = make_float2(acc[mt][nt][0] + bx, acc[mt][nt][1] + by);
            *(float2*)(p + 8 * TE) = make_float2(acc[mt][nt][2] + bx, acc[mt][nt][3] + by);
        }
    }
#undef ISSUE_STAGE
}

// ---------------------------------------------------------------------------
// Attention-column kernel v9: v8 pipeline + smem diet for TRUE 2 CTAs/SM.
//  R16 lesson: 2x(116224 + ~1024 reserved) > 233472 -> only 1 CTA/SM resided.
//  den2 and invd go fp32 (denominator rel-error ~1e-7: washed regime).
//  smem = 64K(Es) + 16K(Q) + 32K(K x2) + 512(den) + 256(invd) = 115456
//  -> 2x(115456+1024) = 232960 < 233472 -> 2 CTAs/SM, grid 256 = one wave.
// ---------------------------------------------------------------------------
#define OFF_ES  0
#define OFF_QS  65536
#define OFF_KS  (OFF_QS + 2 * 8192)              // 81920; two 16KB buffers
#define OFF_DEN (OFF_KS + 2 * 16384)             // 114688; fp32[128]
#define OFF_INV (OFF_DEN + 128 * 4)              // 115200; fp32[64]
#define ATTN_SMEM (OFF_INV + 64 * 4)             // 115456

__global__ __launch_bounds__(256, 2) void attn_col_kernel()
{
    extern __shared__ char sm[];
    const uint32_t sb = smem_u32(sm);
    __half* EsH    = (__half*)sm;                // [64][512]
    float*  den2   = (float*)(sm + OFF_DEN);     // [64][2]
    float*  invd   = (float*)(sm + OFF_INV);     // [64]

    const int t = threadIdx.x, lane = t & 31, wid = t >> 5;
    const int wm = wid & 3, wn = wid >> 2;       // wm: 16-row group; wn: 32-col half
    const int bh = blockIdx.x;

    const char* Qg = (const char*)(g_Qs2 + (size_t)bh * TS * 192);
    const char* Kg = (const char*)(g_Ks2 + (size_t)bh * TS * 192);

    double a0 = 0.0, a1 = 0.0;                   // colacc for s = t, t+256

    const uint32_t lrow = lane & 15;
    const uint32_t lcol = (lane >> 4) * 16;
    const int fr = lane >> 2;
    const int fc = (lane & 3) * 2;
    const int segA3[3] = {0, 0, 1};
    const int segB3[3] = {0, 1, 0};

    // loader lanes: row = t>>2 (0..63), 4 x 16B units u = (t&3)*4 + j
    const int ldrow = t >> 2;
    const int ldq   = t & 3;
    uint32_t ldOff[4];
#pragma unroll
    for (int j = 0; j < 4; j++) {
        int u = ldq * 4 + j;
        int seg = u >> 3, wi = (u & 7) * 16;
        ldOff[j] = seg * 8192 + SW128(ldrow * 128 + wi);
    }

#define ISSUE_K(kt_) do {                                                      \
    int _kt = (kt_);                                                           \
    uint32_t _kb = sb + OFF_KS + (_kt & 1) * 16384;                            \
    const char* _src = Kg + (size_t)(_kt * 64 + ldrow) * 384 + ldq * 64;       \
    _Pragma("unroll")                                                          \
    for (int _j = 0; _j < 4; _j++)                                             \
        CP_ASYNC16(_kb + ldOff[_j], _src + _j * 16);                           \
    CP_COMMIT();                                                               \
} while (0)

    for (int qt = 0; qt < 8; qt++) {
        __syncthreads();   // prev colacc's Es/invd reads done
        // Q tile (hi+mid planes of 64 rows)
        {
            const char* src = Qg + (size_t)(qt * 64 + ldrow) * 384 + ldq * 64;
#pragma unroll
            for (int j = 0; j < 4; j++)
                CP_ASYNC16(sb + OFF_QS + ldOff[j], src + j * 16);
        }
        CP_COMMIT();
        if (t < 128) den2[t] = 0.f;
        ISSUE_K(0);
        ISSUE_K(1);

        for (int kt = 0; kt < 8; kt++) {
            if (kt < 7) CP_WAIT1(); else CP_WAIT0();   // Q..K(kt) arrived
            __syncthreads();

            const uint32_t kb = sb + OFF_KS + (kt & 1) * 16384;
            float acc[4][4];
#pragma unroll
            for (int i = 0; i < 4; i++)
#pragma unroll
                for (int k = 0; k < 4; k++) acc[i][k] = 0.f;

#pragma unroll
            for (int ch = 0; ch < 3; ch++) {
                const uint32_t abase = sb + OFF_QS + segA3[ch] * 8192;
                const uint32_t bbase = kb + segB3[ch] * 8192;
#pragma unroll
                for (int kk = 0; kk < 4; kk++) {
                    uint32_t a[4];
                    LDSM_X4(a[0], a[1], a[2], a[3],
                            abase + SW128((wm * 16 + lrow) * 128 + kk * 32 + lcol));
#pragma unroll
                    for (int nt2 = 0; nt2 < 2; nt2++) {
                        uint32_t b[4];
                        LDSM_X4(b[0], b[1], b[2], b[3],
                                bbase + SW128((wn * 32 + nt2 * 16 + lrow) * 128 + kk * 32 + lcol));
                        MMA_16816(acc[nt2 * 2 + 0], a, b[0], b[2]);
                        MMA_16816(acc[nt2 * 2 + 1], a, b[1], b[3]);
                    }
                }
            }

            // epilogue: exp, fp16 Es stores, fp32 row sums
            const int r0 = wm * 16 + fr;
            float d0f = 0.f, d1f = 0.f;
#pragma unroll
            for (int nt = 0; nt < 4; nt++) {
                const int col = kt * 64 + wn * 32 + nt * 8 + fc;
                float e0 = fast_expf(fmaf(acc[nt][0], 0.125f, 1.0f));
                float e1 = fast_expf(fmaf(acc[nt][1], 0.125f, 1.0f));
                float e2 = fast_expf(fmaf(acc[nt][2], 0.125f, 1.0f));
                float e3 = fast_expf(fmaf(acc[nt][3], 0.125f, 1.0f));
                *(__half2*)&EsH[r0 * 512 + col]       = __floats2half2_rn(e0, e1);
                *(__half2*)&EsH[(r0 + 8) * 512 + col] = __floats2half2_rn(e2, e3);
                d0f += e0 + e1;
                d1f += e2 + e3;
            }
            d0f += __shfl_xor_sync(0xffffffffu, d0f, 1);
            d0f += __shfl_xor_sync(0xffffffffu, d0f, 2);
            d1f += __shfl_xor_sync(0xffffffffu, d1f, 1);
            d1f += __shfl_xor_sync(0xffffffffu, d1f, 2);
            if ((lane & 3) == 0) {
                den2[r0 * 2 + wn]       += d0f;
                den2[(r0 + 8) * 2 + wn] += d1f;
            }
            __syncthreads();   // LDSM reads + den2 adds done
            if (kt + 2 < 8) ISSUE_K(kt + 2);
        }

        if (t < 64) invd[t] = 1.0f / (den2[t * 2] + den2[t * 2 + 1]);
        __syncthreads();

#pragma unroll 8
        for (int rr = 0; rr < 64; rr++) {
            double iv = (double)invd[rr];
            a0 = fma((double)__half2float(EsH[rr * 512 + t]),       iv, a0);
            a1 = fma((double)__half2float(EsH[rr * 512 + t + 256]), iv, a1);
        }
    }
#undef ISSUE_K

    g_colpart[(size_t)bh * TS + t]       = a0;
    g_colpart[(size_t)bh * TS + t + 256] = a1;
}

// ---------------------------------------------------------------------------
// col -> log_softmax logits (fp64, deterministic tree reductions)
// ---------------------------------------------------------------------------
__global__ __launch_bounds__(512) void logits_kernel()
{
    __shared__ double red[512];
    const int b = blockIdx.x;
    const int s = threadIdx.x;

    double v = 0.0;
#pragma unroll
    for (int h = 0; h < TH; h++)
        v += g_colpart[((size_t)b * TH + h) * TS + s];

    red[s] = v;
    __syncthreads();
    for (int off = 256; off > 0; off >>= 1) {
        if (s < off) { double o = red[s + off]; if (o > red[s]) red[s] = o; }
        __syncthreads();
    }
    double m = red[0];
    __syncthreads();
    red[s] = exp(v - m);
    __syncthreads();
    for (int off = 256; off > 0; off >>= 1) {
        if (s < off) red[s] += red[s + off];
        __syncthreads();
    }
    double lse = m + log(red[0]);
    g_logits[(size_t)b * TS + s] = v - lse;
}

// ---------------------------------------------------------------------------
// Threefry-2x32 (JAX-exact, PARTITIONABLE): bits = o0 ^ o1, counter (0, i)
// ---------------------------------------------------------------------------
__device__ __forceinline__ void threefry2x32(
    unsigned k0, unsigned k1, unsigned x0, unsigned x1,
    unsigned& o0, unsigned& o1)
{
    const unsigned ks0 = k0, ks1 = k1, ks2 = k0 ^ k1 ^ 0x1BD11BDAu;
    x0 += ks0; x1 += ks1;
#define TF_RND(r) { x0 += x1; x1 = __funnelshift_l(x1, x1, r); x1 ^= x0; }
    TF_RND(13) TF_RND(15) TF_RND(26) TF_RND(6)   x0 += ks1; x1 += ks2 + 1u;
    TF_RND(17) TF_RND(29) TF_RND(16) TF_RND(24)  x0 += ks2; x1 += ks0 + 2u;
    TF_RND(13) TF_RND(15) TF_RND(26) TF_RND(6)   x0 += ks0; x1 += ks1 + 3u;
    TF_RND(17) TF_RND(29) TF_RND(16) TF_RND(24)  x0 += ks1; x1 += ks2 + 4u;
    TF_RND(13) TF_RND(15) TF_RND(26) TF_RND(6)   x0 += ks2; x1 += ks0 + 5u;
#undef TF_RND
    o0 = x0; o1 = x1;
}

// ---------------------------------------------------------------------------
// sample_kernel (validated R9): fp32 fast path + selective fp64 verification
// ---------------------------------------------------------------------------
__global__ __launch_bounds__(256) void sample_kernel(
    const float* __restrict__ tokens, float* __restrict__ out)
{
    const int warp = blockIdx.x * 8 + (threadIdx.x >> 5);   // 0..16383 = b*1024+j
    const int lane = threadIdx.x & 31;
    const int b = warp >> 10;
    const int j = warp & 1023;

    const double* lg = g_logits + (size_t)b * TS;

    float vreg[16];
    float best32 = -3.0e38f;
#pragma unroll
    for (int si = 0; si < 16; si++) {
        int s = lane + si * 32;
        unsigned i = (unsigned)warp * 512u + (unsigned)s;
        unsigned o0, o1;
        threefry2x32(0u, 42u, 0u, i, o0, o1);
        unsigned bits = o0 ^ o1;
        float f = __uint_as_float((bits >> 9) | 0x3f800000u) - 1.0f;
        float u = fmaxf(f, 1.17549435e-38f);
        float g32 = -logf(-logf(u));
        float v32 = g32 + (float)lg[s];
        vreg[si] = v32;
        best32 = fmaxf(best32, v32);
    }
#pragma unroll
    for (int off = 16; off > 0; off >>= 1)
        best32 = fmaxf(best32, __shfl_xor_sync(0xffffffffu, best32, off));

    const float thresh = best32 - 1.0e-4f;
    double best = -1.0e300;
    int    bi   = 0x7fffffff;
#pragma unroll
    for (int si = 0; si < 16; si++) {
        if (vreg[si] >= thresh) {
            int s = lane + si * 32;
            unsigned i = (unsigned)warp * 512u + (unsigned)s;
            unsigned o0, o1;
            threefry2x32(0u, 42u, 0u, i, o0, o1);
            unsigned bits = o0 ^ o1;
            float f = __uint_as_float((bits >> 9) | 0x3f800000u) - 1.0f;
            float u = fmaxf(f, 1.17549435e-38f);
            double g = -log(-log((double)u));
            double v = g + lg[s];
            if (v > best) { best = v; bi = s; }
        }
    }

#pragma unroll
    for (int off = 16; off > 0; off >>= 1) {
        double ov = __shfl_down_sync(0xffffffffu, best, off);
        int    oi = __shfl_down_sync(0xffffffffu, bi,   off);
        if (ov > best || (ov == best && oi < bi)) { best = ov; bi = oi; }
    }

    if (lane == 0)
        out[warp] = tokens[((size_t)b * TS + (size_t)bi) * TE + (size_t)j];
}

// ---------------------------------------------------------------------------
extern "C" void kernel_launch(void* const* d_in, const int* in_sizes, int n_in,
                              void* d_out, int out_size)
{
    (void)in_sizes; (void)n_in; (void)out_size;
    const float* tokens = (const float*)d_in[0];
    const float* Wq     = (const float*)d_in[1];
    const float* bq     = (const float*)d_in[2];
    const float* Wk     = (const float*)d_in[3];
    const float* bk     = (const float*)d_in[4];
    float* out = (float*)d_out;

    cudaFuncSetAttribute(gemm_hmma_kernel,
                         cudaFuncAttributeMaxDynamicSharedMemorySize, GEMM_SMEM);
    cudaFuncSetAttribute(attn_col_kernel,
                         cudaFuncAttributeMaxDynamicSharedMemorySize, ATTN_SMEM);

    split_inputs_kernel<<<10240, 256>>>(tokens, Wq, Wk);            // 0
    gemm_hmma_kernel<<<dim3(8, 64, 2), 256, GEMM_SMEM>>>(bq, bk);   // 1
    split_qk_kernel<<<dim3(8192, 1, 2), 256>>>();                   // 2
    attn_col_kernel<<<256, 256, ATTN_SMEM>>>();                     // 3 <- ncu capture
    logits_kernel<<<16, 512>>>();                                   // 4
    sample_kernel<<<2048, 256>>>(tokens, out);                      // 5
}